// round 1
// baseline (speedup 1.0000x reference)
#include <cuda_runtime.h>

// Problem constants
#define S_TOK 8192      // B*S_LEN tokens
#define DM    1024      // model dim
#define EM    8         // experts
#define HM    4096      // hidden
#define KM    2048      // capacity per expert

// ---------------- scratch (device globals; no allocation allowed) -----------
__device__ float g_scores[EM * S_TOK];            // softmaxed router scores [E,S]
__device__ float g_gating[EM * KM];               // top-K gating values [E,K]
__device__ int   g_idx[EM * KM];                  // top-K token indices [E,K]
__device__ float g_t[(size_t)S_TOK * DM];         // silu(x@cap_w1+b1)
__device__ float g_h[(size_t)EM * KM * HM];       // gelu hidden [E,K,H]

// ---------------- activations ----------------------------------------------
__device__ __forceinline__ float siluf(float v) {
    return v / (1.0f + __expf(-v));
}
__device__ __forceinline__ float geluf(float v) {
    float c = 0.7978845608028654f * (v + 0.044715f * v * v * v);
    return 0.5f * v * (1.0f + tanhf(c));
}

// ---------------- 0: zero y + ones regions ---------------------------------
__global__ void zero_kernel(float4* p, int n4) {
    int i = blockIdx.x * blockDim.x + threadIdx.x;
    if (i < n4) p[i] = make_float4(0.f, 0.f, 0.f, 0.f);
}

// ---------------- 1: router logits + softmax (warp per token) --------------
__global__ void gate_softmax_kernel(const float* __restrict__ x,
                                    const float* __restrict__ gw) {
    int warp = threadIdx.x >> 5, lane = threadIdx.x & 31;
    int s = blockIdx.x * 8 + warp;
    float acc[EM];
#pragma unroll
    for (int e = 0; e < EM; e++) acc[e] = 0.f;
    const float* xr = x + (size_t)s * DM;
    for (int k = lane; k < DM; k += 32) {
        float xv = xr[k];
#pragma unroll
        for (int e = 0; e < EM; e++) acc[e] += xv * gw[e * DM + k];
    }
#pragma unroll
    for (int e = 0; e < EM; e++) {
#pragma unroll
        for (int o = 16; o > 0; o >>= 1)
            acc[e] += __shfl_xor_sync(0xffffffffu, acc[e], o);
    }
    if (lane == 0) {
        float mx = acc[0];
#pragma unroll
        for (int e = 1; e < EM; e++) mx = fmaxf(mx, acc[e]);
        float sum = 0.f;
#pragma unroll
        for (int e = 0; e < EM; e++) { acc[e] = __expf(acc[e] - mx); sum += acc[e]; }
        float inv = 1.0f / sum;
#pragma unroll
        for (int e = 0; e < EM; e++) g_scores[e * S_TOK + s] = acc[e] * inv;
    }
}

// ---------------- 2: exact top-K per expert via full bitonic sort ----------
// Sort 8192 (score, idx) pairs descending by score, ascending idx on ties
// (matches jax.lax.top_k semantics). One block per expert.
__global__ void topk_kernel(float* __restrict__ ones_out) {
    __shared__ float sv[S_TOK];
    __shared__ unsigned short si[S_TOK];
    int e = blockIdx.x;
    int tid = threadIdx.x;
    for (int i = tid; i < S_TOK; i += 1024) {
        sv[i] = g_scores[e * S_TOK + i];
        si[i] = (unsigned short)i;
    }
    __syncthreads();
    for (int k = 2; k <= S_TOK; k <<= 1) {
        for (int j = k >> 1; j > 0; j >>= 1) {
            for (int i = tid; i < S_TOK; i += 1024) {
                int l = i ^ j;
                if (l > i) {
                    float va = sv[i], vl = sv[l];
                    unsigned short ia = si[i], il = si[l];
                    bool before = (va > vl) || (va == vl && ia < il);
                    bool dir = ((i & k) == 0);
                    if (dir ? !before : before) {
                        sv[i] = vl; sv[l] = va;
                        si[i] = il; si[l] = ia;
                    }
                }
            }
            __syncthreads();
        }
    }
    for (int i = tid; i < KM; i += 1024) {
        g_gating[e * KM + i] = sv[i];
        int tok = si[i];
        g_idx[e * KM + i] = tok;
        ones_out[(size_t)tok * EM + e] = 1.0f;
    }
}

// ---------------- 3/5/6: 128x128x8 register-blocked SGEMM ------------------
// MODE 0: C = silu(x @ cap_w1 + b)           -> g_t
// MODE 1: g_h[e] = gelu(gather(x) @ w1[e]+b) (A rows gathered via g_idx)
// MODE 2: atomicAdd scatter: y[idx] += gating * (g_h[e] @ w2[e] + b)
template <int MODE>
__global__ void __launch_bounds__(256, 2)
sgemm_kernel(const float* __restrict__ A, const float* __restrict__ B,
             const float* __restrict__ bias, int M, int N, int Kd,
             float* __restrict__ Y) {
    __shared__ float As[8][128];
    __shared__ float Bs[8][128];
    const int tid = threadIdx.x;
    const int e = blockIdx.z;
    const int* ridx = nullptr;
    float* C = nullptr;
    if (MODE == 0) {
        C = g_t;
    } else if (MODE == 1) {
        B += (size_t)e * Kd * N;
        bias += (size_t)e * N;
        C = g_h + (size_t)e * M * N;
        ridx = g_idx + e * KM;
    } else {
        A = g_h + (size_t)e * M * Kd;
        B += (size_t)e * Kd * N;
        bias += (size_t)e * N;
        ridx = g_idx + e * KM;
    }

    const int aRow = tid >> 1, aCol = (tid & 1) * 4;
    const int bRow = tid >> 5, bCol = (tid & 31) * 4;
    const int gRow = blockIdx.y * 128 + aRow;
    size_t arow = (MODE == 1) ? (size_t)ridx[gRow] : (size_t)gRow;
    const float* Ap = A + arow * Kd + aCol;
    const float* Bp = B + (size_t)bRow * N + blockIdx.x * 128 + bCol;

    const int tx = tid & 15, ty = tid >> 4;
    float acc[8][8];
#pragma unroll
    for (int i = 0; i < 8; i++)
#pragma unroll
        for (int j = 0; j < 8; j++) acc[i][j] = 0.f;

    for (int kt = 0; kt < Kd; kt += 8) {
        float4 av = *(const float4*)(Ap + kt);
        float4 bv = *(const float4*)(Bp + (size_t)kt * N);
        __syncthreads();
        As[aCol + 0][aRow] = av.x;
        As[aCol + 1][aRow] = av.y;
        As[aCol + 2][aRow] = av.z;
        As[aCol + 3][aRow] = av.w;
        *(float4*)&Bs[bRow][bCol] = bv;
        __syncthreads();
#pragma unroll
        for (int k = 0; k < 8; k++) {
            float a[8], b[8];
            *(float4*)(a)     = *(const float4*)&As[k][ty * 8];
            *(float4*)(a + 4) = *(const float4*)&As[k][ty * 8 + 4];
            *(float4*)(b)     = *(const float4*)&Bs[k][tx * 8];
            *(float4*)(b + 4) = *(const float4*)&Bs[k][tx * 8 + 4];
#pragma unroll
            for (int i = 0; i < 8; i++)
#pragma unroll
                for (int j = 0; j < 8; j++)
                    acc[i][j] = fmaf(a[i], b[j], acc[i][j]);
        }
    }

    const int row0 = blockIdx.y * 128 + ty * 8;
    const int col0 = blockIdx.x * 128 + tx * 8;
    float bv[8];
#pragma unroll
    for (int j = 0; j < 8; j++) bv[j] = bias[col0 + j];

    if (MODE == 0) {
#pragma unroll
        for (int i = 0; i < 8; i++) {
            float* Cr = C + (size_t)(row0 + i) * N + col0;
#pragma unroll
            for (int j = 0; j < 8; j++) Cr[j] = siluf(acc[i][j] + bv[j]);
        }
    } else if (MODE == 1) {
#pragma unroll
        for (int i = 0; i < 8; i++) {
            float* Cr = C + (size_t)(row0 + i) * N + col0;
#pragma unroll
            for (int j = 0; j < 8; j++) Cr[j] = geluf(acc[i][j] + bv[j]);
        }
    } else {
#pragma unroll
        for (int i = 0; i < 8; i++) {
            int r = row0 + i;
            int tok = ridx[r];
            float g = g_gating[e * KM + r];
            float* yr = Y + (size_t)tok * DM + col0;
#pragma unroll
            for (int j = 0; j < 8; j++)
                atomicAdd(&yr[j], g * (acc[i][j] + bv[j]));
        }
    }
}

// ---------------- 4: cap = t @ cap_w2 + b2 (warp per token, N=8) -----------
__global__ void cap_out_kernel(const float* __restrict__ w2,
                               const float* __restrict__ b2,
                               float* __restrict__ capO) {
    int warp = threadIdx.x >> 5, lane = threadIdx.x & 31;
    int s = blockIdx.x * 8 + warp;
    float acc[EM];
#pragma unroll
    for (int j = 0; j < EM; j++) acc[j] = 0.f;
    const float* tr = g_t + (size_t)s * DM;
    for (int k = lane; k < DM; k += 32) {
        float tv = tr[k];
#pragma unroll
        for (int j = 0; j < EM; j++) acc[j] += tv * w2[k * EM + j];
    }
#pragma unroll
    for (int j = 0; j < EM; j++) {
#pragma unroll
        for (int o = 16; o > 0; o >>= 1)
            acc[j] += __shfl_xor_sync(0xffffffffu, acc[j], o);
    }
    if (lane == 0) {
#pragma unroll
        for (int j = 0; j < EM; j++) capO[(size_t)s * EM + j] = acc[j] + b2[j];
    }
}

// ---------------- launch -----------------------------------------------------
extern "C" void kernel_launch(void* const* d_in, const int* in_sizes, int n_in,
                              void* d_out, int out_size) {
    const float* x      = (const float*)d_in[0];
    const float* gate_w = (const float*)d_in[1];
    const float* cap_w1 = (const float*)d_in[2];
    const float* cap_b1 = (const float*)d_in[3];
    const float* cap_w2 = (const float*)d_in[4];
    const float* cap_b2 = (const float*)d_in[5];
    const float* exp_w1 = (const float*)d_in[6];
    const float* exp_b1 = (const float*)d_in[7];
    const float* exp_w2 = (const float*)d_in[8];
    const float* exp_b2 = (const float*)d_in[9];

    float* out  = (float*)d_out;
    float* y    = out;                                   // [S, D]
    float* ones = out + (size_t)S_TOK * DM;              // [S, E]
    float* cap  = ones + (size_t)S_TOK * EM;             // [S, E]

    // zero y + ones (cap fully overwritten)
    int n4 = (S_TOK * DM + S_TOK * EM) / 4;
    zero_kernel<<<(n4 + 255) / 256, 256>>>((float4*)out, n4);

    // router softmax scores [E, S]
    gate_softmax_kernel<<<S_TOK / 8, 256>>>(x, gate_w);

    // exact per-expert top-K (writes gating, idx, ones)
    topk_kernel<<<EM, 1024>>>(ones);

    // capacity predictor: t = silu(x @ cap_w1 + b1); cap = t @ cap_w2 + b2
    sgemm_kernel<0><<<dim3(DM / 128, S_TOK / 128, 1), 256>>>(
        x, cap_w1, cap_b1, S_TOK, DM, DM, nullptr);
    cap_out_kernel<<<S_TOK / 8, 256>>>(cap_w2, cap_b2, cap);

    // expert MLP up-projection with fused gather + GELU
    sgemm_kernel<1><<<dim3(HM / 128, KM / 128, EM), 256>>>(
        x, exp_w1, exp_b1, KM, HM, DM, nullptr);

    // expert MLP down-projection with fused gating-scale + scatter-add
    sgemm_kernel<2><<<dim3(DM / 128, KM / 128, EM), 256>>>(
        nullptr, exp_w2, exp_b2, KM, DM, HM, y);
}

// round 3
// speedup vs baseline: 2.6469x; 2.6469x over previous
#include <cuda_runtime.h>
#include <cstdint>

// Problem constants
#define S_TOK 8192      // B*S_LEN tokens
#define DM    1024      // model dim
#define EM    8         // experts
#define HM    4096      // hidden
#define KM    2048      // capacity per expert

#define KC    16        // k-chunk
#define PITCH 20        // smem row pitch (floats) -> conflict-free frag loads

// ---------------- scratch (device globals; no allocation allowed) -----------
__device__ float g_scores[EM * S_TOK];             // softmaxed router scores [E,S]
__device__ float g_gating[EM * KM];                // top-K gating values [E,K]
__device__ int   g_idx[EM * KM];                   // top-K token indices [E,K]
__device__ float g_t[(size_t)S_TOK * DM];          // silu(x@cap_w1+b1)
__device__ float g_h[(size_t)EM * KM * HM];        // gelu hidden [E,K,H]
__device__ float g_cw1t[(size_t)DM * DM];          // cap_w1^T [Dout, Din]
__device__ float g_w1t[(size_t)EM * HM * DM];      // w1^T per expert [H, D]
__device__ float g_w2t[(size_t)EM * DM * HM];      // w2^T per expert [D, H]

// ---------------- activations ----------------------------------------------
__device__ __forceinline__ float siluf(float v) {
    return v / (1.0f + __expf(-v));
}
__device__ __forceinline__ float geluf(float v) {
    float c = 0.7978845608028654f * (v + 0.044715f * v * v * v);
    return 0.5f * v * (1.0f + tanhf(c));
}
__device__ __forceinline__ uint32_t f2tf32(float v) {
    uint32_t r;
    asm("cvt.rna.tf32.f32 %0, %1;" : "=r"(r) : "f"(v));
    return r;
}
__device__ __forceinline__ void mma_tf32(float* d, const uint32_t* a, const uint32_t* b) {
    asm volatile(
        "mma.sync.aligned.m16n8k8.row.col.f32.tf32.tf32.f32 "
        "{%0,%1,%2,%3}, {%4,%5,%6,%7}, {%8,%9}, {%0,%1,%2,%3};"
        : "+f"(d[0]), "+f"(d[1]), "+f"(d[2]), "+f"(d[3])
        : "r"(a[0]), "r"(a[1]), "r"(a[2]), "r"(a[3]), "r"(b[0]), "r"(b[1]));
}

// ---------------- 0: zero y + ones regions ----------------------------------
__global__ void zero_kernel(float4* p, int n4) {
    int i = blockIdx.x * blockDim.x + threadIdx.x;
    if (i < n4) p[i] = make_float4(0.f, 0.f, 0.f, 0.f);
}

// ---------------- 1: router logits + softmax (warp per token) ---------------
__global__ void gate_softmax_kernel(const float* __restrict__ x,
                                    const float* __restrict__ gw) {
    int warp = threadIdx.x >> 5, lane = threadIdx.x & 31;
    int s = blockIdx.x * 8 + warp;
    float acc[EM];
#pragma unroll
    for (int e = 0; e < EM; e++) acc[e] = 0.f;
    const float* xr = x + (size_t)s * DM;
    for (int k = lane; k < DM; k += 32) {
        float xv = xr[k];
#pragma unroll
        for (int e = 0; e < EM; e++) acc[e] += xv * gw[e * DM + k];
    }
#pragma unroll
    for (int e = 0; e < EM; e++) {
#pragma unroll
        for (int o = 16; o > 0; o >>= 1)
            acc[e] += __shfl_xor_sync(0xffffffffu, acc[e], o);
    }
    if (lane == 0) {
        float mx = acc[0];
#pragma unroll
        for (int e = 1; e < EM; e++) mx = fmaxf(mx, acc[e]);
        float sum = 0.f;
#pragma unroll
        for (int e = 0; e < EM; e++) { acc[e] = __expf(acc[e] - mx); sum += acc[e]; }
        float inv = 1.0f / sum;
#pragma unroll
        for (int e = 0; e < EM; e++) g_scores[e * S_TOK + s] = acc[e] * inv;
    }
}

// ---------------- 2: exact top-K per expert via full bitonic sort -----------
__global__ void topk_kernel(float* __restrict__ ones_out) {
    __shared__ float sv[S_TOK];
    __shared__ unsigned short si[S_TOK];
    int e = blockIdx.x;
    int tid = threadIdx.x;
    for (int i = tid; i < S_TOK; i += 1024) {
        sv[i] = g_scores[e * S_TOK + i];
        si[i] = (unsigned short)i;
    }
    __syncthreads();
    for (int k = 2; k <= S_TOK; k <<= 1) {
        for (int j = k >> 1; j > 0; j >>= 1) {
            for (int i = tid; i < S_TOK; i += 1024) {
                int l = i ^ j;
                if (l > i) {
                    float va = sv[i], vl = sv[l];
                    unsigned short ia = si[i], il = si[l];
                    bool before = (va > vl) || (va == vl && ia < il);
                    bool dir = ((i & k) == 0);
                    if (dir ? !before : before) {
                        sv[i] = vl; sv[l] = va;
                        si[i] = il; si[l] = ia;
                    }
                }
            }
            __syncthreads();
        }
    }
    for (int i = tid; i < KM; i += 1024) {
        g_gating[e * KM + i] = sv[i];
        int tok = si[i];
        g_idx[e * KM + i] = tok;
        ones_out[(size_t)tok * EM + e] = 1.0f;
    }
}

// ---------------- 3: tiled transpose: out[c][r] = in[r][c] ------------------
__global__ void transpose_kernel(const float* __restrict__ in,
                                 float* __restrict__ out, int R, int C) {
    __shared__ float tile[32][33];
    const float* ine = in + (size_t)blockIdx.z * R * C;
    float* oute = out + (size_t)blockIdx.z * R * C;
    int bx = blockIdx.x * 32, by = blockIdx.y * 32;
    int tx = threadIdx.x, ty = threadIdx.y;
#pragma unroll
    for (int i = 0; i < 32; i += 8)
        tile[ty + i][tx] = ine[(size_t)(by + ty + i) * C + bx + tx];
    __syncthreads();
#pragma unroll
    for (int i = 0; i < 32; i += 8)
        oute[(size_t)(bx + ty + i) * R + by + tx] = tile[tx][ty + i];
}

// ---------------- 4: TF32 mma.sync GEMM, 128x128 tile, kc=16 ----------------
// MODE 0: C = silu(A @ B^T + bias)              A = x          -> g_t
// MODE 1: C = gelu(gather(A) @ B^T + bias)      A = x (g_idx)  -> g_h[e]
// MODE 2: y[idx] += gating * (A @ B^T + bias)   A = g_h[e]     -> Y (atomic)
// Bw is K-major [N, K]. 8 warps, warp tile 64(M) x 32(N), m16n8k8 frags.
template <int MODE>
__global__ void __launch_bounds__(256, 2)
mma_gemm(const float* __restrict__ A, const float* __restrict__ Bw,
         const float* __restrict__ bias, float* __restrict__ Cout,
         int M, int N, int K) {
    __shared__ uint32_t sA[2][128 * PITCH];
    __shared__ uint32_t sB[2][128 * PITCH];

    const int t = threadIdx.x;
    const int lane = t & 31, w = t >> 5;
    const int wm = w & 1, wn = w >> 1;             // warp tile: rows wm*64, cols wn*32
    const int g = lane >> 2, tg = lane & 3;
    const int e = blockIdx.z;
    const int row0 = blockIdx.y * 128;
    const int col0 = blockIdx.x * 128;

    if (MODE == 1) {
        Bw += (size_t)e * N * K;
        bias += (size_t)e * N;
        Cout += (size_t)e * (size_t)M * N;
    } else if (MODE == 2) {
        A += (size_t)e * (size_t)M * K;
        Bw += (size_t)e * N * K;
        bias += (size_t)e * N;
    }

    // loader assignment: 512 float4 per matrix per chunk, 2 per thread
    const float* aptr[2];
    const float* bptr[2];
    int soff[2];
#pragma unroll
    for (int j = 0; j < 2; j++) {
        int i = t + j * 256;
        int row = i >> 2, c4 = i & 3;
        soff[j] = row * PITCH + c4 * 4;
        long arow = row0 + row;
        if (MODE == 1) arow = g_idx[e * KM + arow];
        aptr[j] = A + (size_t)arow * K + c4 * 4;
        bptr[j] = Bw + (size_t)(col0 + row) * K + c4 * 4;
    }

    float acc[4][4][4];
#pragma unroll
    for (int mt = 0; mt < 4; mt++)
#pragma unroll
        for (int nt = 0; nt < 4; nt++)
#pragma unroll
            for (int r = 0; r < 4; r++) acc[mt][nt][r] = 0.f;

    const int NC = K / KC;
    float4 av[2], bv[2];
#pragma unroll
    for (int j = 0; j < 2; j++) {
        av[j] = *(const float4*)(aptr[j]);
        bv[j] = *(const float4*)(bptr[j]);
    }

    for (int c = 0; c < NC; c++) {
        const int s = c & 1;
#pragma unroll
        for (int j = 0; j < 2; j++) {
            uint32_t* da = &sA[s][soff[j]];
            da[0] = f2tf32(av[j].x); da[1] = f2tf32(av[j].y);
            da[2] = f2tf32(av[j].z); da[3] = f2tf32(av[j].w);
            uint32_t* db = &sB[s][soff[j]];
            db[0] = f2tf32(bv[j].x); db[1] = f2tf32(bv[j].y);
            db[2] = f2tf32(bv[j].z); db[3] = f2tf32(bv[j].w);
        }
        __syncthreads();
        if (c + 1 < NC) {
            const int kb = (c + 1) * KC;
#pragma unroll
            for (int j = 0; j < 2; j++) {
                av[j] = *(const float4*)(aptr[j] + kb);
                bv[j] = *(const float4*)(bptr[j] + kb);
            }
        }
#pragma unroll
        for (int ks = 0; ks < 2; ks++) {
            const int k0 = ks * 8;
            uint32_t af[4][4], bf[4][2];
#pragma unroll
            for (int mt = 0; mt < 4; mt++) {
                int r_lo = wm * 64 + mt * 16 + g;
                af[mt][0] = sA[s][r_lo * PITCH + k0 + tg];
                af[mt][1] = sA[s][(r_lo + 8) * PITCH + k0 + tg];
                af[mt][2] = sA[s][r_lo * PITCH + k0 + tg + 4];
                af[mt][3] = sA[s][(r_lo + 8) * PITCH + k0 + tg + 4];
            }
#pragma unroll
            for (int nt = 0; nt < 4; nt++) {
                int n = wn * 32 + nt * 8 + g;
                bf[nt][0] = sB[s][n * PITCH + k0 + tg];
                bf[nt][1] = sB[s][n * PITCH + k0 + tg + 4];
            }
#pragma unroll
            for (int mt = 0; mt < 4; mt++)
#pragma unroll
                for (int nt = 0; nt < 4; nt++)
                    mma_tf32(acc[mt][nt], af[mt], bf[nt]);
        }
        __syncthreads();
    }

    // ---------------- epilogue ----------------
#pragma unroll
    for (int mt = 0; mt < 4; mt++) {
        int r_lo = row0 + wm * 64 + mt * 16 + g;
        int r_hi = r_lo + 8;
        int tok_lo = 0, tok_hi = 0;
        float g_lo = 0.f, g_hi = 0.f;
        if (MODE == 2) {
            tok_lo = g_idx[e * KM + r_lo];
            tok_hi = g_idx[e * KM + r_hi];
            g_lo = g_gating[e * KM + r_lo];
            g_hi = g_gating[e * KM + r_hi];
        }
#pragma unroll
        for (int nt = 0; nt < 4; nt++) {
            int col = col0 + wn * 32 + nt * 8 + 2 * tg;
            float b0 = bias[col], b1 = bias[col + 1];
            float v0 = acc[mt][nt][0] + b0, v1 = acc[mt][nt][1] + b1;
            float v2 = acc[mt][nt][2] + b0, v3 = acc[mt][nt][3] + b1;
            if (MODE == 0) {
                *(float2*)(Cout + (size_t)r_lo * N + col) = make_float2(siluf(v0), siluf(v1));
                *(float2*)(Cout + (size_t)r_hi * N + col) = make_float2(siluf(v2), siluf(v3));
            } else if (MODE == 1) {
                *(float2*)(Cout + (size_t)r_lo * N + col) = make_float2(geluf(v0), geluf(v1));
                *(float2*)(Cout + (size_t)r_hi * N + col) = make_float2(geluf(v2), geluf(v3));
            } else {
                float* ylo = Cout + (size_t)tok_lo * DM + col;
                float* yhi = Cout + (size_t)tok_hi * DM + col;
                atomicAdd(ylo, g_lo * v0);
                atomicAdd(ylo + 1, g_lo * v1);
                atomicAdd(yhi, g_hi * v2);
                atomicAdd(yhi + 1, g_hi * v3);
            }
        }
    }
}

// ---------------- 5: cap = t @ cap_w2 + b2 (warp per token, N=8) ------------
__global__ void cap_out_kernel(const float* __restrict__ w2,
                               const float* __restrict__ b2,
                               float* __restrict__ capO) {
    int warp = threadIdx.x >> 5, lane = threadIdx.x & 31;
    int s = blockIdx.x * 8 + warp;
    float acc[EM];
#pragma unroll
    for (int j = 0; j < EM; j++) acc[j] = 0.f;
    const float* tr = g_t + (size_t)s * DM;
    for (int k = lane; k < DM; k += 32) {
        float tv = tr[k];
#pragma unroll
        for (int j = 0; j < EM; j++) acc[j] += tv * w2[k * EM + j];
    }
#pragma unroll
    for (int j = 0; j < EM; j++) {
#pragma unroll
        for (int o = 16; o > 0; o >>= 1)
            acc[j] += __shfl_xor_sync(0xffffffffu, acc[j], o);
    }
    if (lane == 0) {
#pragma unroll
        for (int j = 0; j < EM; j++) capO[(size_t)s * EM + j] = acc[j] + b2[j];
    }
}

// ---------------- launch -----------------------------------------------------
extern "C" void kernel_launch(void* const* d_in, const int* in_sizes, int n_in,
                              void* d_out, int out_size) {
    const float* x      = (const float*)d_in[0];
    const float* gate_w = (const float*)d_in[1];
    const float* cap_w1 = (const float*)d_in[2];
    const float* cap_b1 = (const float*)d_in[3];
    const float* cap_w2 = (const float*)d_in[4];
    const float* cap_b2 = (const float*)d_in[5];
    const float* exp_w1 = (const float*)d_in[6];
    const float* exp_b1 = (const float*)d_in[7];
    const float* exp_w2 = (const float*)d_in[8];
    const float* exp_b2 = (const float*)d_in[9];

    float* out  = (float*)d_out;
    float* y    = out;                                   // [S, D]
    float* ones = out + (size_t)S_TOK * DM;              // [S, E]
    float* cap  = ones + (size_t)S_TOK * EM;             // [S, E]

    // zero y + ones (cap fully overwritten)
    int n4 = (S_TOK * DM + S_TOK * EM) / 4;
    zero_kernel<<<(n4 + 255) / 256, 256>>>((float4*)out, n4);

    // router softmax scores [E, S]
    gate_softmax_kernel<<<S_TOK / 8, 256>>>(x, gate_w);

    // exact per-expert top-K (writes gating, idx, ones)
    topk_kernel<<<EM, 1024>>>(ones);

    // weight transposes to K-major
    float* cw1t; cudaGetSymbolAddress((void**)&cw1t, g_cw1t);
    float* w1t;  cudaGetSymbolAddress((void**)&w1t, g_w1t);
    float* w2t;  cudaGetSymbolAddress((void**)&w2t, g_w2t);
    float* gt;   cudaGetSymbolAddress((void**)&gt, g_t);
    float* gh;   cudaGetSymbolAddress((void**)&gh, g_h);
    transpose_kernel<<<dim3(DM / 32, DM / 32, 1), dim3(32, 8)>>>(cap_w1, cw1t, DM, DM);
    transpose_kernel<<<dim3(HM / 32, DM / 32, EM), dim3(32, 8)>>>(exp_w1, w1t, DM, HM);
    transpose_kernel<<<dim3(DM / 32, HM / 32, EM), dim3(32, 8)>>>(exp_w2, w2t, HM, DM);

    // capacity predictor: t = silu(x @ cap_w1 + b1); cap = t @ cap_w2 + b2
    mma_gemm<0><<<dim3(DM / 128, S_TOK / 128, 1), 256>>>(
        x, cw1t, cap_b1, gt, S_TOK, DM, DM);
    cap_out_kernel<<<S_TOK / 8, 256>>>(cap_w2, cap_b2, cap);

    // expert MLP up-projection: gather + GELU
    mma_gemm<1><<<dim3(HM / 128, KM / 128, EM), 256>>>(
        x, w1t, exp_b1, gh, KM, HM, DM);

    // expert MLP down-projection: gating-scale + scatter-add
    mma_gemm<2><<<dim3(DM / 128, KM / 128, EM), 256>>>(
        gh, w2t, exp_b2, y, KM, DM, HM);
}

// round 4
// speedup vs baseline: 5.2715x; 1.9916x over previous
#include <cuda_runtime.h>
#include <cuda_fp16.h>
#include <cstdint>

// Problem constants
#define S_TOK 8192      // B*S_LEN tokens
#define DM    1024      // model dim
#define EM    8         // experts
#define HM    4096      // hidden
#define KM    2048      // capacity per expert

#define KC    32        // k-chunk (elements)
#define PH    40        // smem row pitch in halves (80B): ldmatrix conflict-free

// ---------------- scratch (device globals; no allocation allowed) -----------
__device__ float  g_scores[EM * S_TOK];            // softmaxed router scores [E,S]
__device__ float  g_gating[EM * KM];               // top-K gating values [E,K]
__device__ int    g_idx[EM * KM];                  // top-K token indices [E,K]
__device__ float  g_t[(size_t)S_TOK * DM];         // silu(x@cap_w1+b1) fp32
__device__ __half g_h[(size_t)EM * KM * HM];       // gelu hidden [E,K,H] fp16
__device__ __half g_cw1t[(size_t)DM * DM];         // cap_w1^T [Dout, Din] fp16
__device__ __half g_w1t[(size_t)EM * HM * DM];     // w1^T per expert [H, D] fp16
__device__ __half g_w2t[(size_t)EM * DM * HM];     // w2^T per expert [D, H] fp16

// ---------------- activations ----------------------------------------------
__device__ __forceinline__ float siluf(float v) {
    return v / (1.0f + __expf(-v));
}
__device__ __forceinline__ float geluf(float v) {
    float c = 0.7978845608028654f * (v + 0.044715f * v * v * v);
    return 0.5f * v * (1.0f + tanhf(c));
}
__device__ __forceinline__ void ldm_x4(uint32_t* r, uint32_t addr) {
    asm volatile("ldmatrix.sync.aligned.m8n8.x4.shared.b16 {%0,%1,%2,%3}, [%4];"
                 : "=r"(r[0]), "=r"(r[1]), "=r"(r[2]), "=r"(r[3]) : "r"(addr));
}
__device__ __forceinline__ void mma_f16(float* d, const uint32_t* a, const uint32_t* b) {
    asm volatile(
        "mma.sync.aligned.m16n8k16.row.col.f32.f16.f16.f32 "
        "{%0,%1,%2,%3}, {%4,%5,%6,%7}, {%8,%9}, {%0,%1,%2,%3};"
        : "+f"(d[0]), "+f"(d[1]), "+f"(d[2]), "+f"(d[3])
        : "r"(a[0]), "r"(a[1]), "r"(a[2]), "r"(a[3]), "r"(b[0]), "r"(b[1]));
}

// ---------------- 0: zero y + ones regions ----------------------------------
__global__ void zero_kernel(float4* p, int n4) {
    int i = blockIdx.x * blockDim.x + threadIdx.x;
    if (i < n4) p[i] = make_float4(0.f, 0.f, 0.f, 0.f);
}

// ---------------- 1: router logits + softmax (warp per token) ---------------
__global__ void gate_softmax_kernel(const float* __restrict__ x,
                                    const float* __restrict__ gw) {
    int warp = threadIdx.x >> 5, lane = threadIdx.x & 31;
    int s = blockIdx.x * 8 + warp;
    float acc[EM];
#pragma unroll
    for (int e = 0; e < EM; e++) acc[e] = 0.f;
    const float* xr = x + (size_t)s * DM;
    for (int k = lane; k < DM; k += 32) {
        float xv = xr[k];
#pragma unroll
        for (int e = 0; e < EM; e++) acc[e] += xv * gw[e * DM + k];
    }
#pragma unroll
    for (int e = 0; e < EM; e++) {
#pragma unroll
        for (int o = 16; o > 0; o >>= 1)
            acc[e] += __shfl_xor_sync(0xffffffffu, acc[e], o);
    }
    if (lane == 0) {
        float mx = acc[0];
#pragma unroll
        for (int e = 1; e < EM; e++) mx = fmaxf(mx, acc[e]);
        float sum = 0.f;
#pragma unroll
        for (int e = 0; e < EM; e++) { acc[e] = __expf(acc[e] - mx); sum += acc[e]; }
        float inv = 1.0f / sum;
#pragma unroll
        for (int e = 0; e < EM; e++) g_scores[e * S_TOK + s] = acc[e] * inv;
    }
}

// ---------------- 2: exact top-K per expert via full bitonic sort -----------
__global__ void topk_kernel(float* __restrict__ ones_out) {
    __shared__ float sv[S_TOK];
    __shared__ unsigned short si[S_TOK];
    int e = blockIdx.x;
    int tid = threadIdx.x;
    for (int i = tid; i < S_TOK; i += 1024) {
        sv[i] = g_scores[e * S_TOK + i];
        si[i] = (unsigned short)i;
    }
    __syncthreads();
    for (int k = 2; k <= S_TOK; k <<= 1) {
        for (int j = k >> 1; j > 0; j >>= 1) {
            for (int i = tid; i < S_TOK; i += 1024) {
                int l = i ^ j;
                if (l > i) {
                    float va = sv[i], vl = sv[l];
                    unsigned short ia = si[i], il = si[l];
                    bool before = (va > vl) || (va == vl && ia < il);
                    bool dir = ((i & k) == 0);
                    if (dir ? !before : before) {
                        sv[i] = vl; sv[l] = va;
                        si[i] = il; si[l] = ia;
                    }
                }
            }
            __syncthreads();
        }
    }
    for (int i = tid; i < KM; i += 1024) {
        g_gating[e * KM + i] = sv[i];
        int tok = si[i];
        g_idx[e * KM + i] = tok;
        ones_out[(size_t)tok * EM + e] = 1.0f;
    }
}

// ------------- 3: fused transpose + f32->f16: out[c][r] = half(in[r][c]) ----
__global__ void transpose_h_kernel(const float* __restrict__ in,
                                   __half* __restrict__ out, int R, int C) {
    __shared__ float tile[32][33];
    const float* ine = in + (size_t)blockIdx.z * R * C;
    __half* oute = out + (size_t)blockIdx.z * R * C;
    int bx = blockIdx.x * 32, by = blockIdx.y * 32;
    int tx = threadIdx.x, ty = threadIdx.y;
#pragma unroll
    for (int i = 0; i < 32; i += 8)
        tile[ty + i][tx] = ine[(size_t)(by + ty + i) * C + bx + tx];
    __syncthreads();
#pragma unroll
    for (int i = 0; i < 32; i += 8)
        oute[(size_t)(bx + ty + i) * R + by + tx] = __float2half_rn(tile[tx][ty + i]);
}

// ---------------- 4: FP16 mma.sync GEMM, 128x128 tile, kc=32 ----------------
// MODE 0: g_t = silu(x @ B^T + bias)            (A fp32, C fp32)
// MODE 1: g_h[e] = gelu(gather(x) @ B^T + bias) (A fp32 gathered, C fp16)
// MODE 2: y[idx] += gating * (g_h[e] @ B^T + b) (A fp16, C fp32 atomic)
// Bw is K-major fp16 [N, K]. 8 warps, warp tile 64(M) x 32(N), m16n8k16.
template <int MODE>
__global__ void __launch_bounds__(256, 2)
hgemm(const void* __restrict__ A_, const __half* __restrict__ Bw,
      const float* __restrict__ bias, void* __restrict__ C_,
      int M, int N, int K) {
    __shared__ __align__(16) __half sA[2][128 * PH];
    __shared__ __align__(16) __half sB[2][128 * PH];

    const int t = threadIdx.x;
    const int lane = t & 31, w = t >> 5;
    const int wm = w & 1, wn = w >> 1;             // warp tile rows wm*64, cols wn*32
    const int g = lane >> 2, tg = lane & 3;
    const int e = blockIdx.z;
    const int row0 = blockIdx.y * 128;
    const int col0 = blockIdx.x * 128;

    const float* Af = (const float*)A_;
    const __half* Ah = (const __half*)A_;
    if (MODE == 1) {
        Bw += (size_t)e * N * K;
        bias += (size_t)e * N;
    } else if (MODE == 2) {
        Ah += (size_t)e * (size_t)M * K;
        Bw += (size_t)e * N * K;
        bias += (size_t)e * N;
    }

    // ---- loader setup ----
    // A fp32 (MODE 0/1): 4 segs, thread j: row=i>>3, 4 floats at c8*4
    // A fp16 (MODE 2):   2 segs, thread j: row=i>>2, 8 halves at c16*8
    const float* agf[4];
    const __half* agh[2];
    int aoff[4];
    if (MODE <= 1) {
#pragma unroll
        for (int j = 0; j < 4; j++) {
            int i = t + j * 256;
            int row = i >> 3, c8 = i & 7;
            aoff[j] = row * PH + c8 * 4;
            long arow = row0 + row;
            if (MODE == 1) arow = g_idx[e * KM + arow];
            agf[j] = Af + (size_t)arow * K + c8 * 4;
        }
    } else {
#pragma unroll
        for (int j = 0; j < 2; j++) {
            int i = t + j * 256;
            int row = i >> 2, c16 = i & 3;
            aoff[j] = row * PH + c16 * 8;
            agh[j] = Ah + (size_t)(row0 + row) * K + c16 * 8;
        }
    }
    const __half* bgh[2];
    int boff[2];
#pragma unroll
    for (int j = 0; j < 2; j++) {
        int i = t + j * 256;
        int row = i >> 2, c16 = i & 3;
        boff[j] = row * PH + c16 * 8;
        bgh[j] = Bw + (size_t)(col0 + row) * K + c16 * 8;
    }

    // frag smem offsets (halves)
    const int a_fr = (wm * 64 + (lane & 15)) * PH + (lane >> 4) * 8;
    const int b_fr = ((lane >> 4) * 8 + (lane & 7)) * PH + ((lane >> 3) & 1) * 8;

    float acc[4][4][4];
#pragma unroll
    for (int mt = 0; mt < 4; mt++)
#pragma unroll
        for (int nt = 0; nt < 4; nt++)
#pragma unroll
            for (int r = 0; r < 4; r++) acc[mt][nt][r] = 0.f;

    const int NC = K / KC;
    float4 avf[4];
    uint4 avh[2], bvh[2];
    if (MODE <= 1) {
#pragma unroll
        for (int j = 0; j < 4; j++) avf[j] = *(const float4*)(agf[j]);
    } else {
#pragma unroll
        for (int j = 0; j < 2; j++) avh[j] = *(const uint4*)(agh[j]);
    }
#pragma unroll
    for (int j = 0; j < 2; j++) bvh[j] = *(const uint4*)(bgh[j]);

    for (int c = 0; c < NC; c++) {
        const int s = c & 1;
        // stores
        if (MODE <= 1) {
#pragma unroll
            for (int j = 0; j < 4; j++) {
                __half2 h01 = __floats2half2_rn(avf[j].x, avf[j].y);
                __half2 h23 = __floats2half2_rn(avf[j].z, avf[j].w);
                uint2 pk = make_uint2(*(uint32_t*)&h01, *(uint32_t*)&h23);
                *(uint2*)&sA[s][aoff[j]] = pk;
            }
        } else {
#pragma unroll
            for (int j = 0; j < 2; j++) *(uint4*)&sA[s][aoff[j]] = avh[j];
        }
#pragma unroll
        for (int j = 0; j < 2; j++) *(uint4*)&sB[s][boff[j]] = bvh[j];
        __syncthreads();
        if (c + 1 < NC) {
            const int kb = (c + 1) * KC;
            if (MODE <= 1) {
#pragma unroll
                for (int j = 0; j < 4; j++) avf[j] = *(const float4*)(agf[j] + kb);
            } else {
#pragma unroll
                for (int j = 0; j < 2; j++) avh[j] = *(const uint4*)(agh[j] + kb);
            }
#pragma unroll
            for (int j = 0; j < 2; j++) bvh[j] = *(const uint4*)(bgh[j] + kb);
        }
        // compute: 2 k16 steps
        uint32_t sa_base = (uint32_t)__cvta_generic_to_shared(&sA[s][0]);
        uint32_t sb_base = (uint32_t)__cvta_generic_to_shared(&sB[s][0]);
#pragma unroll
        for (int ks = 0; ks < 2; ks++) {
            uint32_t af[4][4], bf[4][2];
#pragma unroll
            for (int mt = 0; mt < 4; mt++)
                ldm_x4(af[mt], sa_base + 2 * (a_fr + mt * 16 * PH + ks * 16));
#pragma unroll
            for (int p = 0; p < 2; p++) {
                uint32_t r4[4];
                ldm_x4(r4, sb_base + 2 * (b_fr + (wn * 32 + p * 16) * PH + ks * 16));
                bf[p * 2][0] = r4[0]; bf[p * 2][1] = r4[1];
                bf[p * 2 + 1][0] = r4[2]; bf[p * 2 + 1][1] = r4[3];
            }
#pragma unroll
            for (int mt = 0; mt < 4; mt++)
#pragma unroll
                for (int nt = 0; nt < 4; nt++)
                    mma_f16(acc[mt][nt], af[mt], bf[nt]);
        }
        __syncthreads();
    }

    // ---------------- epilogue ----------------
#pragma unroll
    for (int mt = 0; mt < 4; mt++) {
        int r_lo = row0 + wm * 64 + mt * 16 + g;
        int r_hi = r_lo + 8;
        int tok_lo = 0, tok_hi = 0;
        float g_lo = 0.f, g_hi = 0.f;
        if (MODE == 2) {
            tok_lo = g_idx[e * KM + r_lo];
            tok_hi = g_idx[e * KM + r_hi];
            g_lo = g_gating[e * KM + r_lo];
            g_hi = g_gating[e * KM + r_hi];
        }
#pragma unroll
        for (int nt = 0; nt < 4; nt++) {
            int col = col0 + wn * 32 + nt * 8 + 2 * tg;
            float b0 = bias[col], b1 = bias[col + 1];
            float v0 = acc[mt][nt][0] + b0, v1 = acc[mt][nt][1] + b1;
            float v2 = acc[mt][nt][2] + b0, v3 = acc[mt][nt][3] + b1;
            if (MODE == 0) {
                float* Co = (float*)C_;
                *(float2*)(Co + (size_t)r_lo * N + col) = make_float2(siluf(v0), siluf(v1));
                *(float2*)(Co + (size_t)r_hi * N + col) = make_float2(siluf(v2), siluf(v3));
            } else if (MODE == 1) {
                __half* Co = (__half*)C_ + (size_t)e * (size_t)M * N;
                __half2 lo = __floats2half2_rn(geluf(v0), geluf(v1));
                __half2 hi = __floats2half2_rn(geluf(v2), geluf(v3));
                *(__half2*)(Co + (size_t)r_lo * N + col) = lo;
                *(__half2*)(Co + (size_t)r_hi * N + col) = hi;
            } else {
                float* Co = (float*)C_;
                float* ylo = Co + (size_t)tok_lo * DM + col;
                float* yhi = Co + (size_t)tok_hi * DM + col;
                atomicAdd(ylo, g_lo * v0);
                atomicAdd(ylo + 1, g_lo * v1);
                atomicAdd(yhi, g_hi * v2);
                atomicAdd(yhi + 1, g_hi * v3);
            }
        }
    }
}

// ---------------- 5: cap = t @ cap_w2 + b2 (warp per token, N=8) ------------
__global__ void cap_out_kernel(const float* __restrict__ w2,
                               const float* __restrict__ b2,
                               float* __restrict__ capO) {
    int warp = threadIdx.x >> 5, lane = threadIdx.x & 31;
    int s = blockIdx.x * 8 + warp;
    float acc[EM];
#pragma unroll
    for (int j = 0; j < EM; j++) acc[j] = 0.f;
    const float* tr = g_t + (size_t)s * DM;
    for (int k = lane; k < DM; k += 32) {
        float tv = tr[k];
#pragma unroll
        for (int j = 0; j < EM; j++) acc[j] += tv * w2[k * EM + j];
    }
#pragma unroll
    for (int j = 0; j < EM; j++) {
#pragma unroll
        for (int o = 16; o > 0; o >>= 1)
            acc[j] += __shfl_xor_sync(0xffffffffu, acc[j], o);
    }
    if (lane == 0) {
#pragma unroll
        for (int j = 0; j < EM; j++) capO[(size_t)s * EM + j] = acc[j] + b2[j];
    }
}

// ---------------- launch -----------------------------------------------------
extern "C" void kernel_launch(void* const* d_in, const int* in_sizes, int n_in,
                              void* d_out, int out_size) {
    const float* x      = (const float*)d_in[0];
    const float* gate_w = (const float*)d_in[1];
    const float* cap_w1 = (const float*)d_in[2];
    const float* cap_b1 = (const float*)d_in[3];
    const float* cap_w2 = (const float*)d_in[4];
    const float* cap_b2 = (const float*)d_in[5];
    const float* exp_w1 = (const float*)d_in[6];
    const float* exp_b1 = (const float*)d_in[7];
    const float* exp_w2 = (const float*)d_in[8];
    const float* exp_b2 = (const float*)d_in[9];

    float* out  = (float*)d_out;
    float* y    = out;                                   // [S, D]
    float* ones = out + (size_t)S_TOK * DM;              // [S, E]
    float* cap  = ones + (size_t)S_TOK * EM;             // [S, E]

    // zero y + ones (cap fully overwritten)
    int n4 = (S_TOK * DM + S_TOK * EM) / 4;
    zero_kernel<<<(n4 + 255) / 256, 256>>>((float4*)out, n4);

    // router softmax scores [E, S]
    gate_softmax_kernel<<<S_TOK / 8, 256>>>(x, gate_w);

    // exact per-expert top-K (writes gating, idx, ones)
    topk_kernel<<<EM, 1024>>>(ones);

    // weight transposes to K-major fp16
    __half* cw1t; cudaGetSymbolAddress((void**)&cw1t, g_cw1t);
    __half* w1t;  cudaGetSymbolAddress((void**)&w1t, g_w1t);
    __half* w2t;  cudaGetSymbolAddress((void**)&w2t, g_w2t);
    float*  gt;   cudaGetSymbolAddress((void**)&gt, g_t);
    __half* gh;   cudaGetSymbolAddress((void**)&gh, g_h);
    transpose_h_kernel<<<dim3(DM / 32, DM / 32, 1), dim3(32, 8)>>>(cap_w1, cw1t, DM, DM);
    transpose_h_kernel<<<dim3(HM / 32, DM / 32, EM), dim3(32, 8)>>>(exp_w1, w1t, DM, HM);
    transpose_h_kernel<<<dim3(DM / 32, HM / 32, EM), dim3(32, 8)>>>(exp_w2, w2t, HM, DM);

    // capacity predictor: t = silu(x @ cap_w1 + b1); cap = t @ cap_w2 + b2
    hgemm<0><<<dim3(DM / 128, S_TOK / 128, 1), 256>>>(
        x, cw1t, cap_b1, gt, S_TOK, DM, DM);
    cap_out_kernel<<<S_TOK / 8, 256>>>(cap_w2, cap_b2, cap);

    // expert MLP up-projection: gather + GELU -> fp16 hidden
    hgemm<1><<<dim3(HM / 128, KM / 128, EM), 256>>>(
        x, w1t, exp_b1, gh, KM, HM, DM);

    // expert MLP down-projection: gating-scale + scatter-add
    hgemm<2><<<dim3(DM / 128, KM / 128, EM), 256>>>(
        gh, w2t, exp_b2, y, KM, DM, HM);
}

// round 5
// speedup vs baseline: 5.8560x; 1.1109x over previous
#include <cuda_runtime.h>
#include <cuda_fp16.h>
#include <cstdint>

// Problem constants
#define S_TOK 8192      // B*S_LEN tokens
#define DM    1024      // model dim
#define EM    8         // experts
#define HM    4096      // hidden
#define KM    2048      // capacity per expert

#define KC        32            // k-chunk (halves)
#define STAGEB    24576         // 8KB A + 16KB B per stage
#define NSTAGE    3
#define SMEM_DYN  (NSTAGE * STAGEB + 1024)

// ---------------- scratch (device globals; no allocation allowed) -----------
__device__ float  g_scores[EM * S_TOK];            // softmaxed router scores [E,S]
__device__ float  g_gating[EM * KM];               // top-K gating values [E,K]
__device__ int    g_idx[EM * KM];                  // top-K token indices [E,K]
__device__ float  g_t[(size_t)S_TOK * DM];         // silu(x@cap_w1+b1) fp32
__device__ __half g_xh[(size_t)S_TOK * DM];        // x in fp16
__device__ __half g_h[(size_t)EM * KM * HM];       // gelu hidden [E,K,H] fp16
__device__ __half g_cw1t[(size_t)DM * DM];         // cap_w1^T fp16
__device__ __half g_w1t[(size_t)EM * HM * DM];     // w1^T per expert [H, D] fp16
__device__ __half g_w2t[(size_t)EM * DM * HM];     // w2^T per expert [D, H] fp16

// ---------------- helpers ----------------------------------------------------
__device__ __forceinline__ float siluf(float v) {
    return v / (1.0f + __expf(-v));
}
__device__ __forceinline__ float geluf(float v) {
    float c = 0.7978845608028654f * (v + 0.044715f * v * v * v);
    return 0.5f * v * (1.0f + tanhf(c));
}
__device__ __forceinline__ void ldm_x4(uint32_t* r, uint32_t addr) {
    asm volatile("ldmatrix.sync.aligned.m8n8.x4.shared.b16 {%0,%1,%2,%3}, [%4];"
                 : "=r"(r[0]), "=r"(r[1]), "=r"(r[2]), "=r"(r[3]) : "r"(addr));
}
__device__ __forceinline__ void mma_f16(float* d, const uint32_t* a, const uint32_t* b) {
    asm volatile(
        "mma.sync.aligned.m16n8k16.row.col.f32.f16.f16.f32 "
        "{%0,%1,%2,%3}, {%4,%5,%6,%7}, {%8,%9}, {%0,%1,%2,%3};"
        : "+f"(d[0]), "+f"(d[1]), "+f"(d[2]), "+f"(d[3])
        : "r"(a[0]), "r"(a[1]), "r"(a[2]), "r"(a[3]), "r"(b[0]), "r"(b[1]));
}
__device__ __forceinline__ void cp16(uint32_t dst, const void* src) {
    asm volatile("cp.async.cg.shared.global [%0], [%1], 16;" :: "r"(dst), "l"(src));
}
__device__ __forceinline__ void cp_commit() {
    asm volatile("cp.async.commit_group;");
}
__device__ __forceinline__ void cp_wait1() {
    asm volatile("cp.async.wait_group 1;");
}
__device__ __forceinline__ uint32_t swzi(uint32_t off) {      // SW128: b[6:4]^=b[9:7]
    return off ^ ((off >> 3) & 0x70);
}

// ---------------- 0: zero y + ones regions ----------------------------------
__global__ void zero_kernel(float4* p, int n4) {
    int i = blockIdx.x * blockDim.x + threadIdx.x;
    if (i < n4) p[i] = make_float4(0.f, 0.f, 0.f, 0.f);
}

// ---------------- 0b: x -> fp16 ---------------------------------------------
__global__ void x2h_kernel(const float4* __restrict__ x, uint2* __restrict__ xh, int n8) {
    int i = blockIdx.x * blockDim.x + threadIdx.x;
    if (i < n8) {
        float4 a = x[i * 2], b = x[i * 2 + 1];
        __half2 h0 = __floats2half2_rn(a.x, a.y);
        __half2 h1 = __floats2half2_rn(a.z, a.w);
        __half2 h2 = __floats2half2_rn(b.x, b.y);
        __half2 h3 = __floats2half2_rn(b.z, b.w);
        uint2 lo = make_uint2(*(uint32_t*)&h0, *(uint32_t*)&h1);
        uint2 hi = make_uint2(*(uint32_t*)&h2, *(uint32_t*)&h3);
        xh[i * 2] = lo;
        xh[i * 2 + 1] = hi;
    }
}

// ---------------- 1: router logits + softmax (warp per token) ---------------
__global__ void gate_softmax_kernel(const float* __restrict__ x,
                                    const float* __restrict__ gw) {
    int warp = threadIdx.x >> 5, lane = threadIdx.x & 31;
    int s = blockIdx.x * 8 + warp;
    float acc[EM];
#pragma unroll
    for (int e = 0; e < EM; e++) acc[e] = 0.f;
    const float* xr = x + (size_t)s * DM;
    for (int k = lane; k < DM; k += 32) {
        float xv = xr[k];
#pragma unroll
        for (int e = 0; e < EM; e++) acc[e] += xv * gw[e * DM + k];
    }
#pragma unroll
    for (int e = 0; e < EM; e++) {
#pragma unroll
        for (int o = 16; o > 0; o >>= 1)
            acc[e] += __shfl_xor_sync(0xffffffffu, acc[e], o);
    }
    if (lane == 0) {
        float mx = acc[0];
#pragma unroll
        for (int e = 1; e < EM; e++) mx = fmaxf(mx, acc[e]);
        float sum = 0.f;
#pragma unroll
        for (int e = 0; e < EM; e++) { acc[e] = __expf(acc[e] - mx); sum += acc[e]; }
        float inv = 1.0f / sum;
#pragma unroll
        for (int e = 0; e < EM; e++) g_scores[e * S_TOK + s] = acc[e] * inv;
    }
}

// ---------------- 2: exact top-K per expert via full bitonic sort -----------
__global__ void topk_kernel(float* __restrict__ ones_out) {
    __shared__ float sv[S_TOK];
    __shared__ unsigned short si[S_TOK];
    int e = blockIdx.x;
    int tid = threadIdx.x;
    for (int i = tid; i < S_TOK; i += 1024) {
        sv[i] = g_scores[e * S_TOK + i];
        si[i] = (unsigned short)i;
    }
    __syncthreads();
    for (int k = 2; k <= S_TOK; k <<= 1) {
        for (int j = k >> 1; j > 0; j >>= 1) {
            for (int i = tid; i < S_TOK; i += 1024) {
                int l = i ^ j;
                if (l > i) {
                    float va = sv[i], vl = sv[l];
                    unsigned short ia = si[i], il = si[l];
                    bool before = (va > vl) || (va == vl && ia < il);
                    bool dir = ((i & k) == 0);
                    if (dir ? !before : before) {
                        sv[i] = vl; sv[l] = va;
                        si[i] = il; si[l] = ia;
                    }
                }
            }
            __syncthreads();
        }
    }
    for (int i = tid; i < KM; i += 1024) {
        g_gating[e * KM + i] = sv[i];
        int tok = si[i];
        g_idx[e * KM + i] = tok;
        ones_out[(size_t)tok * EM + e] = 1.0f;
    }
}

// ------------- 3: fused transpose + f32->f16 ---------------------------------
__global__ void transpose_h_kernel(const float* __restrict__ in,
                                   __half* __restrict__ out, int R, int C) {
    __shared__ float tile[32][33];
    const float* ine = in + (size_t)blockIdx.z * R * C;
    __half* oute = out + (size_t)blockIdx.z * R * C;
    int bx = blockIdx.x * 32, by = blockIdx.y * 32;
    int tx = threadIdx.x, ty = threadIdx.y;
#pragma unroll
    for (int i = 0; i < 32; i += 8)
        tile[ty + i][tx] = ine[(size_t)(by + ty + i) * C + bx + tx];
    __syncthreads();
#pragma unroll
    for (int i = 0; i < 32; i += 8)
        oute[(size_t)(bx + ty + i) * R + by + tx] = __float2half_rn(tile[tx][ty + i]);
}

// ------------- 4: FP16 HMMA GEMM, 128(M)x256(N) tile, kc=32, cp.async x3 ----
// MODE 0: g_t = silu(xh @ B^T + bias)            (fp32 out)
// MODE 1: g_h[e] = gelu(gather(xh) @ B^T + bias) (fp16 out)
// MODE 2: y[idx] += gating * (g_h[e] @ B^T + b)  (fp32 atomic out)
// A fp16 [*, K]; Bw fp16 K-major [N, K]. 8 warps, warp tile 64x64.
template <int MODE>
__global__ void __launch_bounds__(256, 1)
hgemm(const __half* __restrict__ A, const __half* __restrict__ Bw,
      const float* __restrict__ bias, void* __restrict__ C_,
      int M, int N, int K) {
    extern __shared__ char dynsmem[];
    uint32_t base = (uint32_t)__cvta_generic_to_shared(dynsmem);
    base = (base + 1023u) & ~1023u;

    const int t = threadIdx.x;
    const int lane = t & 31, w = t >> 5;
    const int wm = w & 1, wn = w >> 1;          // warp tile: rows wm*64, cols wn*64
    const int g = lane >> 2, tg = lane & 3;
    const int e = blockIdx.z;
    const int row0 = blockIdx.y * 128;
    const int col0 = blockIdx.x * 256;

    if (MODE == 1) {
        Bw += (size_t)e * N * K;
        bias += (size_t)e * N;
    } else if (MODE == 2) {
        A += (size_t)e * (size_t)M * K;
        Bw += (size_t)e * N * K;
        bias += (size_t)e * N;
    }

    // ---- cp.async loader setup: A 512 16B-chunks (2/thr), B 1024 (4/thr) ----
    const __half* a_src[2];
    uint32_t a_dst[2];
#pragma unroll
    for (int j = 0; j < 2; j++) {
        int i = t + j * 256;
        int row = i >> 2, u = i & 3;
        a_dst[j] = swzi((uint32_t)(row * 64 + u * 16));
        long arow = row0 + row;
        if (MODE == 1) arow = g_idx[e * KM + arow];
        a_src[j] = A + (size_t)arow * K + u * 8;
    }
    const __half* b_src[4];
    uint32_t b_dst[4];
#pragma unroll
    for (int j = 0; j < 4; j++) {
        int i = t + j * 256;
        int row = i >> 2, u = i & 3;
        b_dst[j] = swzi((uint32_t)(row * 64 + u * 16));
        b_src[j] = Bw + (size_t)(col0 + row) * K + u * 8;
    }

    float acc[4][8][4];
#pragma unroll
    for (int mt = 0; mt < 4; mt++)
#pragma unroll
        for (int nt = 0; nt < 8; nt++)
#pragma unroll
            for (int r = 0; r < 4; r++) acc[mt][nt][r] = 0.f;

    const int NC = K / KC;

    // prologue: stage 0, 1
#pragma unroll
    for (int st = 0; st < 2; st++) {
        uint32_t ab = base + st * STAGEB;
        uint32_t bb = ab + 8192;
        int kb = st * KC;
#pragma unroll
        for (int j = 0; j < 2; j++) cp16(ab + a_dst[j], a_src[j] + kb);
#pragma unroll
        for (int j = 0; j < 4; j++) cp16(bb + b_dst[j], b_src[j] + kb);
        cp_commit();
    }

    for (int c = 0; c < NC; c++) {
        cp_wait1();
        __syncthreads();
        if (c + 2 < NC) {
            int st = (c + 2) % NSTAGE;
            uint32_t ab = base + st * STAGEB;
            uint32_t bb = ab + 8192;
            int kb = (c + 2) * KC;
#pragma unroll
            for (int j = 0; j < 2; j++) cp16(ab + a_dst[j], a_src[j] + kb);
#pragma unroll
            for (int j = 0; j < 4; j++) cp16(bb + b_dst[j], b_src[j] + kb);
        }
        cp_commit();

        uint32_t sa = base + (c % NSTAGE) * STAGEB;
        uint32_t sb = sa + 8192;
#pragma unroll
        for (int ks = 0; ks < 2; ks++) {
            uint32_t af[4][4], bf[8][2];
            int aunit = (lane >> 4) + ks * 2;
#pragma unroll
            for (int mt = 0; mt < 4; mt++) {
                int r = wm * 64 + mt * 16 + (lane & 15);
                ldm_x4(af[mt], sa + swzi((uint32_t)(r * 64 + aunit * 16)));
            }
            int brow = wn * 64 + ((lane >> 4) << 3) + (lane & 7);
            int bunit = ks * 2 + ((lane >> 3) & 1);
#pragma unroll
            for (int p = 0; p < 4; p++) {
                uint32_t r4[4];
                int r = brow + p * 16;
                ldm_x4(r4, sb + swzi((uint32_t)(r * 64 + bunit * 16)));
                bf[p * 2][0] = r4[0]; bf[p * 2][1] = r4[1];
                bf[p * 2 + 1][0] = r4[2]; bf[p * 2 + 1][1] = r4[3];
            }
#pragma unroll
            for (int mt = 0; mt < 4; mt++)
#pragma unroll
                for (int nt = 0; nt < 8; nt++)
                    mma_f16(acc[mt][nt], af[mt], bf[nt]);
        }
        __syncthreads();
    }

    // ---------------- epilogue ----------------
#pragma unroll
    for (int mt = 0; mt < 4; mt++) {
        int r_lo = row0 + wm * 64 + mt * 16 + g;
        int r_hi = r_lo + 8;
        int tok_lo = 0, tok_hi = 0;
        float g_lo = 0.f, g_hi = 0.f;
        if (MODE == 2) {
            tok_lo = g_idx[e * KM + r_lo];
            tok_hi = g_idx[e * KM + r_hi];
            g_lo = g_gating[e * KM + r_lo];
            g_hi = g_gating[e * KM + r_hi];
        }
#pragma unroll
        for (int nt = 0; nt < 8; nt++) {
            int col = col0 + wn * 64 + nt * 8 + 2 * tg;
            float b0 = bias[col], b1 = bias[col + 1];
            float v0 = acc[mt][nt][0] + b0, v1 = acc[mt][nt][1] + b1;
            float v2 = acc[mt][nt][2] + b0, v3 = acc[mt][nt][3] + b1;
            if (MODE == 0) {
                float* Co = (float*)C_;
                *(float2*)(Co + (size_t)r_lo * N + col) = make_float2(siluf(v0), siluf(v1));
                *(float2*)(Co + (size_t)r_hi * N + col) = make_float2(siluf(v2), siluf(v3));
            } else if (MODE == 1) {
                __half* Co = (__half*)C_ + (size_t)e * (size_t)M * N;
                __half2 lo = __floats2half2_rn(geluf(v0), geluf(v1));
                __half2 hi = __floats2half2_rn(geluf(v2), geluf(v3));
                *(__half2*)(Co + (size_t)r_lo * N + col) = lo;
                *(__half2*)(Co + (size_t)r_hi * N + col) = hi;
            } else {
                float* Co = (float*)C_;
                float* ylo = Co + (size_t)tok_lo * DM + col;
                float* yhi = Co + (size_t)tok_hi * DM + col;
                atomicAdd(ylo, g_lo * v0);
                atomicAdd(ylo + 1, g_lo * v1);
                atomicAdd(yhi, g_hi * v2);
                atomicAdd(yhi + 1, g_hi * v3);
            }
        }
    }
}

// ---------------- 5: cap = t @ cap_w2 + b2 (warp per token, N=8) ------------
__global__ void cap_out_kernel(const float* __restrict__ w2,
                               const float* __restrict__ b2,
                               float* __restrict__ capO) {
    int warp = threadIdx.x >> 5, lane = threadIdx.x & 31;
    int s = blockIdx.x * 8 + warp;
    float acc[EM];
#pragma unroll
    for (int j = 0; j < EM; j++) acc[j] = 0.f;
    const float* tr = g_t + (size_t)s * DM;
    for (int k = lane; k < DM; k += 32) {
        float tv = tr[k];
#pragma unroll
        for (int j = 0; j < EM; j++) acc[j] += tv * w2[k * EM + j];
    }
#pragma unroll
    for (int j = 0; j < EM; j++) {
#pragma unroll
        for (int o = 16; o > 0; o >>= 1)
            acc[j] += __shfl_xor_sync(0xffffffffu, acc[j], o);
    }
    if (lane == 0) {
#pragma unroll
        for (int j = 0; j < EM; j++) capO[(size_t)s * EM + j] = acc[j] + b2[j];
    }
}

// ---------------- launch -----------------------------------------------------
extern "C" void kernel_launch(void* const* d_in, const int* in_sizes, int n_in,
                              void* d_out, int out_size) {
    const float* x      = (const float*)d_in[0];
    const float* gate_w = (const float*)d_in[1];
    const float* cap_w1 = (const float*)d_in[2];
    const float* cap_b1 = (const float*)d_in[3];
    const float* cap_w2 = (const float*)d_in[4];
    const float* cap_b2 = (const float*)d_in[5];
    const float* exp_w1 = (const float*)d_in[6];
    const float* exp_b1 = (const float*)d_in[7];
    const float* exp_w2 = (const float*)d_in[8];
    const float* exp_b2 = (const float*)d_in[9];

    float* out  = (float*)d_out;
    float* y    = out;                                   // [S, D]
    float* ones = out + (size_t)S_TOK * DM;              // [S, E]
    float* cap  = ones + (size_t)S_TOK * EM;             // [S, E]

    cudaFuncSetAttribute(hgemm<0>, cudaFuncAttributeMaxDynamicSharedMemorySize, SMEM_DYN);
    cudaFuncSetAttribute(hgemm<1>, cudaFuncAttributeMaxDynamicSharedMemorySize, SMEM_DYN);
    cudaFuncSetAttribute(hgemm<2>, cudaFuncAttributeMaxDynamicSharedMemorySize, SMEM_DYN);

    // zero y + ones (cap fully overwritten)
    int n4 = (S_TOK * DM + S_TOK * EM) / 4;
    zero_kernel<<<(n4 + 255) / 256, 256>>>((float4*)out, n4);

    // x -> fp16
    __half* xh; cudaGetSymbolAddress((void**)&xh, g_xh);
    x2h_kernel<<<(S_TOK * DM / 8 + 255) / 256, 256>>>((const float4*)x, (uint2*)xh,
                                                      S_TOK * DM / 8);

    // router softmax scores [E, S]
    gate_softmax_kernel<<<S_TOK / 8, 256>>>(x, gate_w);

    // exact per-expert top-K (writes gating, idx, ones)
    topk_kernel<<<EM, 1024>>>(ones);

    // weight transposes to K-major fp16
    __half* cw1t; cudaGetSymbolAddress((void**)&cw1t, g_cw1t);
    __half* w1t;  cudaGetSymbolAddress((void**)&w1t, g_w1t);
    __half* w2t;  cudaGetSymbolAddress((void**)&w2t, g_w2t);
    float*  gt;   cudaGetSymbolAddress((void**)&gt, g_t);
    __half* gh;   cudaGetSymbolAddress((void**)&gh, g_h);
    transpose_h_kernel<<<dim3(DM / 32, DM / 32, 1), dim3(32, 8)>>>(cap_w1, cw1t, DM, DM);
    transpose_h_kernel<<<dim3(HM / 32, DM / 32, EM), dim3(32, 8)>>>(exp_w1, w1t, DM, HM);
    transpose_h_kernel<<<dim3(DM / 32, HM / 32, EM), dim3(32, 8)>>>(exp_w2, w2t, HM, DM);

    // capacity predictor: t = silu(x @ cap_w1 + b1); cap = t @ cap_w2 + b2
    hgemm<0><<<dim3(DM / 256, S_TOK / 128, 1), 256, SMEM_DYN>>>(
        xh, cw1t, cap_b1, gt, S_TOK, DM, DM);
    cap_out_kernel<<<S_TOK / 8, 256>>>(cap_w2, cap_b2, cap);

    // expert MLP up-projection: gather + GELU -> fp16 hidden
    hgemm<1><<<dim3(HM / 256, KM / 128, EM), 256, SMEM_DYN>>>(
        xh, w1t, exp_b1, gh, KM, HM, DM);

    // expert MLP down-projection: gating-scale + scatter-add
    hgemm<2><<<dim3(DM / 256, KM / 128, EM), 256, SMEM_DYN>>>(
        gh, w2t, exp_b2, y, KM, DM, HM);
}

// round 6
// speedup vs baseline: 6.1200x; 1.0451x over previous
#include <cuda_runtime.h>
#include <cuda_fp16.h>
#include <cstdint>

// Problem constants
#define S_TOK 8192      // B*S_LEN tokens
#define DM    1024      // model dim
#define EM    8         // experts
#define HM    4096      // hidden
#define KM    2048      // capacity per expert

#define KC        32            // k-chunk (halves)
#define STAGEB    24576         // 8KB A + 16KB B per stage
#define NSTAGE    3
#define SMEM_DYN  (NSTAGE * STAGEB + 1024)

// ---------------- scratch (device globals; no allocation allowed) -----------
__device__ float  g_scores[EM * S_TOK];            // softmaxed router scores [E,S]
__device__ float  g_gating[EM * KM];               // top-K gating values [E,K]
__device__ int    g_idx[EM * KM];                  // top-K token indices [E,K]
__device__ float  g_t[(size_t)S_TOK * DM];         // silu(x@cap_w1+b1) fp32
__device__ __half g_xh[(size_t)S_TOK * DM];        // x in fp16
__device__ __half g_h[(size_t)EM * KM * HM];       // gelu hidden [E,K,H] fp16
__device__ __half g_cw1t[(size_t)DM * DM];         // cap_w1^T fp16
__device__ __half g_w1t[(size_t)EM * HM * DM];     // w1^T per expert [H, D] fp16
__device__ __half g_w2t[(size_t)EM * DM * HM];     // w2^T per expert [D, H] fp16

// ---------------- helpers ----------------------------------------------------
__device__ __forceinline__ float siluf(float v) {
    return v / (1.0f + __expf(-v));
}
__device__ __forceinline__ float geluf(float v) {
    float c = 0.7978845608028654f * (v + 0.044715f * v * v * v);
    return 0.5f * v * (1.0f + tanhf(c));
}
__device__ __forceinline__ void ldm_x4(uint32_t* r, uint32_t addr) {
    asm volatile("ldmatrix.sync.aligned.m8n8.x4.shared.b16 {%0,%1,%2,%3}, [%4];"
                 : "=r"(r[0]), "=r"(r[1]), "=r"(r[2]), "=r"(r[3]) : "r"(addr));
}
__device__ __forceinline__ void mma_f16(float* d, const uint32_t* a, const uint32_t* b) {
    asm volatile(
        "mma.sync.aligned.m16n8k16.row.col.f32.f16.f16.f32 "
        "{%0,%1,%2,%3}, {%4,%5,%6,%7}, {%8,%9}, {%0,%1,%2,%3};"
        : "+f"(d[0]), "+f"(d[1]), "+f"(d[2]), "+f"(d[3])
        : "r"(a[0]), "r"(a[1]), "r"(a[2]), "r"(a[3]), "r"(b[0]), "r"(b[1]));
}
__device__ __forceinline__ void cp16(uint32_t dst, const void* src) {
    asm volatile("cp.async.cg.shared.global [%0], [%1], 16;" :: "r"(dst), "l"(src));
}
__device__ __forceinline__ void cp_commit() {
    asm volatile("cp.async.commit_group;");
}
__device__ __forceinline__ void cp_wait1() {
    asm volatile("cp.async.wait_group 1;");
}
__device__ __forceinline__ uint32_t swzi(uint32_t off) {      // SW128: b[6:4]^=b[9:7]
    return off ^ ((off >> 3) & 0x70);
}

// ---------------- 0: zero y + ones regions ----------------------------------
__global__ void zero_kernel(float4* p, int n4) {
    int i = blockIdx.x * blockDim.x + threadIdx.x;
    if (i < n4) p[i] = make_float4(0.f, 0.f, 0.f, 0.f);
}

// ---------------- 0b: x -> fp16 ---------------------------------------------
__global__ void x2h_kernel(const float4* __restrict__ x, uint2* __restrict__ xh, int n8) {
    int i = blockIdx.x * blockDim.x + threadIdx.x;
    if (i < n8) {
        float4 a = x[i * 2], b = x[i * 2 + 1];
        __half2 h0 = __floats2half2_rn(a.x, a.y);
        __half2 h1 = __floats2half2_rn(a.z, a.w);
        __half2 h2 = __floats2half2_rn(b.x, b.y);
        __half2 h3 = __floats2half2_rn(b.z, b.w);
        uint2 lo = make_uint2(*(uint32_t*)&h0, *(uint32_t*)&h1);
        uint2 hi = make_uint2(*(uint32_t*)&h2, *(uint32_t*)&h3);
        xh[i * 2] = lo;
        xh[i * 2 + 1] = hi;
    }
}

// ---------------- 1: router logits + softmax (warp per token) ---------------
__global__ void gate_softmax_kernel(const float* __restrict__ x,
                                    const float* __restrict__ gw) {
    int warp = threadIdx.x >> 5, lane = threadIdx.x & 31;
    int s = blockIdx.x * 8 + warp;
    float acc[EM];
#pragma unroll
    for (int e = 0; e < EM; e++) acc[e] = 0.f;
    const float* xr = x + (size_t)s * DM;
    for (int k = lane; k < DM; k += 32) {
        float xv = xr[k];
#pragma unroll
        for (int e = 0; e < EM; e++) acc[e] += xv * gw[e * DM + k];
    }
#pragma unroll
    for (int e = 0; e < EM; e++) {
#pragma unroll
        for (int o = 16; o > 0; o >>= 1)
            acc[e] += __shfl_xor_sync(0xffffffffu, acc[e], o);
    }
    if (lane == 0) {
        float mx = acc[0];
#pragma unroll
        for (int e = 1; e < EM; e++) mx = fmaxf(mx, acc[e]);
        float sum = 0.f;
#pragma unroll
        for (int e = 0; e < EM; e++) { acc[e] = __expf(acc[e] - mx); sum += acc[e]; }
        float inv = 1.0f / sum;
#pragma unroll
        for (int e = 0; e < EM; e++) g_scores[e * S_TOK + s] = acc[e] * inv;
    }
}

// ---------------- 2: exact top-K per expert via 3-level radix select --------
// Scores are softmax outputs (positive) => float order == uint bit order.
// Output order within the K slots is irrelevant (scatter-add combine); the
// selected SET matches jax.lax.top_k exactly, ties broken by smaller index.
__global__ void topk_select_kernel(float* __restrict__ ones_out) {
    __shared__ uint32_t keys[S_TOK];   // 32KB
    __shared__ uint32_t hist[2048];    // 8KB
    __shared__ uint32_t sb_sel;
    __shared__ int s_pos;
    const int e = blockIdx.x;
    const int tid = threadIdx.x;

    for (int i = tid; i < S_TOK; i += 1024)
        keys[i] = __float_as_uint(g_scores[e * S_TOK + i]);
    if (tid == 0) s_pos = 0;

    uint32_t prefix = 0, prefmask = 0;
    int need = KM;
    const int shifts[3] = {21, 10, 0};
    const int binsN[3] = {2048, 2048, 1024};
    const uint32_t bmask[3] = {2047u, 2047u, 1023u};

#pragma unroll
    for (int lev = 0; lev < 3; lev++) {
        const int nb = binsN[lev];
        __syncthreads();
        for (int i = tid; i < nb; i += 1024) hist[i] = 0;
        __syncthreads();
        for (int i = tid; i < S_TOK; i += 1024) {
            uint32_t k = keys[i];
            if ((k & prefmask) == prefix)
                atomicAdd(&hist[(k >> shifts[lev]) & bmask[lev]], 1u);
        }
        __syncthreads();
        // inclusive suffix sum over hist
        for (int off = 1; off < nb; off <<= 1) {
            uint32_t v0 = 0, v1 = 0;
            int i0 = tid, i1 = tid + 1024;
            if (i0 < nb) v0 = hist[i0] + ((i0 + off < nb) ? hist[i0 + off] : 0u);
            if (i1 < nb) v1 = hist[i1] + ((i1 + off < nb) ? hist[i1 + off] : 0u);
            __syncthreads();
            if (i0 < nb) hist[i0] = v0;
            if (i1 < nb) hist[i1] = v1;
            __syncthreads();
        }
        // find bin b: S(b) >= need > S(b+1)
        for (int i = tid; i < nb; i += 1024) {
            uint32_t s = hist[i];
            uint32_t snx = (i + 1 < nb) ? hist[i + 1] : 0u;
            if (s >= (uint32_t)need && snx < (uint32_t)need) sb_sel = (uint32_t)i;
        }
        __syncthreads();
        uint32_t b = sb_sel;
        uint32_t snx = (b + 1 < (uint32_t)nb) ? hist[b + 1] : 0u;
        need -= (int)snx;
        prefix |= b << shifts[lev];
        prefmask |= bmask[lev] << shifts[lev];
    }
    __syncthreads();

    const uint32_t T = prefix;   // exact K-th value (as bits)
    const int R = need;          // how many of the == T keys to take (smallest idx)
    for (int i = tid; i < S_TOK; i += 1024) {
        uint32_t k = keys[i];
        bool sel = (k > T);
        if (!sel && k == T) {
            int rank = 0;
            for (int j = 0; j < i; j++)
                if (keys[j] == T) rank++;
            sel = (rank < R);
        }
        if (sel) {
            int p = atomicAdd(&s_pos, 1);
            g_gating[e * KM + p] = __uint_as_float(k);
            g_idx[e * KM + p] = i;
            ones_out[(size_t)i * EM + e] = 1.0f;
        }
    }
}

// ------------- 3: vectorized 64x64 transpose + f32->f16 ---------------------
// out[c][r] = half(in[r][c]); R, C multiples of 64.
__global__ void transpose_h_kernel(const float* __restrict__ in,
                                   __half* __restrict__ out, int R, int C) {
    __shared__ float tile[64][65];
    const float* ine = in + (size_t)blockIdx.z * R * C;
    __half* oute = out + (size_t)blockIdx.z * R * C;
    const int bx = blockIdx.x * 64;   // col base (C dim)
    const int by = blockIdx.y * 64;   // row base (R dim)
    const int t = threadIdx.x;        // 256 threads
#pragma unroll
    for (int j = 0; j < 4; j++) {
        int i = t + j * 256;
        int r = i >> 4, c4 = (i & 15) * 4;
        float4 v = *(const float4*)(ine + (size_t)(by + r) * C + bx + c4);
        tile[r][c4 + 0] = v.x; tile[r][c4 + 1] = v.y;
        tile[r][c4 + 2] = v.z; tile[r][c4 + 3] = v.w;
    }
    __syncthreads();
#pragma unroll
    for (int j = 0; j < 2; j++) {
        int i = t + j * 256;
        int c = i >> 3, r8 = (i & 7) * 8;
        __half2 p0 = __floats2half2_rn(tile[r8 + 0][c], tile[r8 + 1][c]);
        __half2 p1 = __floats2half2_rn(tile[r8 + 2][c], tile[r8 + 3][c]);
        __half2 p2 = __floats2half2_rn(tile[r8 + 4][c], tile[r8 + 5][c]);
        __half2 p3 = __floats2half2_rn(tile[r8 + 6][c], tile[r8 + 7][c]);
        uint4 pk = make_uint4(*(uint32_t*)&p0, *(uint32_t*)&p1,
                              *(uint32_t*)&p2, *(uint32_t*)&p3);
        *(uint4*)(oute + (size_t)(bx + c) * R + by + r8) = pk;
    }
}

// ------------- 4: FP16 HMMA GEMM, 128(M)x256(N) tile, kc=32, cp.async x3 ----
// MODE 0: g_t = silu(xh @ B^T + bias)            (fp32 out)
// MODE 1: g_h[e] = gelu(gather(xh) @ B^T + bias) (fp16 out)
// MODE 2: y[idx] += gating * (g_h[e] @ B^T + b)  (fp32 atomic out)
template <int MODE>
__global__ void __launch_bounds__(256, 1)
hgemm(const __half* __restrict__ A, const __half* __restrict__ Bw,
      const float* __restrict__ bias, void* __restrict__ C_,
      int M, int N, int K) {
    extern __shared__ char dynsmem[];
    uint32_t base = (uint32_t)__cvta_generic_to_shared(dynsmem);
    base = (base + 1023u) & ~1023u;

    const int t = threadIdx.x;
    const int lane = t & 31, w = t >> 5;
    const int wm = w & 1, wn = w >> 1;          // warp tile: rows wm*64, cols wn*64
    const int g = lane >> 2, tg = lane & 3;
    const int e = blockIdx.z;
    const int row0 = blockIdx.y * 128;
    const int col0 = blockIdx.x * 256;

    if (MODE == 1) {
        Bw += (size_t)e * N * K;
        bias += (size_t)e * N;
    } else if (MODE == 2) {
        A += (size_t)e * (size_t)M * K;
        Bw += (size_t)e * N * K;
        bias += (size_t)e * N;
    }

    const __half* a_src[2];
    uint32_t a_dst[2];
#pragma unroll
    for (int j = 0; j < 2; j++) {
        int i = t + j * 256;
        int row = i >> 2, u = i & 3;
        a_dst[j] = swzi((uint32_t)(row * 64 + u * 16));
        long arow = row0 + row;
        if (MODE == 1) arow = g_idx[e * KM + arow];
        a_src[j] = A + (size_t)arow * K + u * 8;
    }
    const __half* b_src[4];
    uint32_t b_dst[4];
#pragma unroll
    for (int j = 0; j < 4; j++) {
        int i = t + j * 256;
        int row = i >> 2, u = i & 3;
        b_dst[j] = swzi((uint32_t)(row * 64 + u * 16));
        b_src[j] = Bw + (size_t)(col0 + row) * K + u * 8;
    }

    float acc[4][8][4];
#pragma unroll
    for (int mt = 0; mt < 4; mt++)
#pragma unroll
        for (int nt = 0; nt < 8; nt++)
#pragma unroll
            for (int r = 0; r < 4; r++) acc[mt][nt][r] = 0.f;

    const int NC = K / KC;

#pragma unroll
    for (int st = 0; st < 2; st++) {
        uint32_t ab = base + st * STAGEB;
        uint32_t bb = ab + 8192;
        int kb = st * KC;
#pragma unroll
        for (int j = 0; j < 2; j++) cp16(ab + a_dst[j], a_src[j] + kb);
#pragma unroll
        for (int j = 0; j < 4; j++) cp16(bb + b_dst[j], b_src[j] + kb);
        cp_commit();
    }

    for (int c = 0; c < NC; c++) {
        cp_wait1();
        __syncthreads();
        if (c + 2 < NC) {
            int st = (c + 2) % NSTAGE;
            uint32_t ab = base + st * STAGEB;
            uint32_t bb = ab + 8192;
            int kb = (c + 2) * KC;
#pragma unroll
            for (int j = 0; j < 2; j++) cp16(ab + a_dst[j], a_src[j] + kb);
#pragma unroll
            for (int j = 0; j < 4; j++) cp16(bb + b_dst[j], b_src[j] + kb);
        }
        cp_commit();

        uint32_t sa = base + (c % NSTAGE) * STAGEB;
        uint32_t sb = sa + 8192;
#pragma unroll
        for (int ks = 0; ks < 2; ks++) {
            uint32_t af[4][4], bf[8][2];
            int aunit = (lane >> 4) + ks * 2;
#pragma unroll
            for (int mt = 0; mt < 4; mt++) {
                int r = wm * 64 + mt * 16 + (lane & 15);
                ldm_x4(af[mt], sa + swzi((uint32_t)(r * 64 + aunit * 16)));
            }
            int brow = wn * 64 + ((lane >> 4) << 3) + (lane & 7);
            int bunit = ks * 2 + ((lane >> 3) & 1);
#pragma unroll
            for (int p = 0; p < 4; p++) {
                uint32_t r4[4];
                int r = brow + p * 16;
                ldm_x4(r4, sb + swzi((uint32_t)(r * 64 + bunit * 16)));
                bf[p * 2][0] = r4[0]; bf[p * 2][1] = r4[1];
                bf[p * 2 + 1][0] = r4[2]; bf[p * 2 + 1][1] = r4[3];
            }
#pragma unroll
            for (int mt = 0; mt < 4; mt++)
#pragma unroll
                for (int nt = 0; nt < 8; nt++)
                    mma_f16(acc[mt][nt], af[mt], bf[nt]);
        }
        __syncthreads();
    }

    // ---------------- epilogue ----------------
#pragma unroll
    for (int mt = 0; mt < 4; mt++) {
        int r_lo = row0 + wm * 64 + mt * 16 + g;
        int r_hi = r_lo + 8;
        int tok_lo = 0, tok_hi = 0;
        float g_lo = 0.f, g_hi = 0.f;
        if (MODE == 2) {
            tok_lo = g_idx[e * KM + r_lo];
            tok_hi = g_idx[e * KM + r_hi];
            g_lo = g_gating[e * KM + r_lo];
            g_hi = g_gating[e * KM + r_hi];
        }
#pragma unroll
        for (int nt = 0; nt < 8; nt++) {
            int col = col0 + wn * 64 + nt * 8 + 2 * tg;
            float b0 = bias[col], b1 = bias[col + 1];
            float v0 = acc[mt][nt][0] + b0, v1 = acc[mt][nt][1] + b1;
            float v2 = acc[mt][nt][2] + b0, v3 = acc[mt][nt][3] + b1;
            if (MODE == 0) {
                float* Co = (float*)C_;
                *(float2*)(Co + (size_t)r_lo * N + col) = make_float2(siluf(v0), siluf(v1));
                *(float2*)(Co + (size_t)r_hi * N + col) = make_float2(siluf(v2), siluf(v3));
            } else if (MODE == 1) {
                __half* Co = (__half*)C_ + (size_t)e * (size_t)M * N;
                __half2 lo = __floats2half2_rn(geluf(v0), geluf(v1));
                __half2 hi = __floats2half2_rn(geluf(v2), geluf(v3));
                *(__half2*)(Co + (size_t)r_lo * N + col) = lo;
                *(__half2*)(Co + (size_t)r_hi * N + col) = hi;
            } else {
                float* Co = (float*)C_;
                float* ylo = Co + (size_t)tok_lo * DM + col;
                float* yhi = Co + (size_t)tok_hi * DM + col;
                atomicAdd(ylo, g_lo * v0);
                atomicAdd(ylo + 1, g_lo * v1);
                atomicAdd(yhi, g_hi * v2);
                atomicAdd(yhi + 1, g_hi * v3);
            }
        }
    }
}

// ---------------- 5: cap = t @ cap_w2 + b2 (warp per token, N=8) ------------
__global__ void cap_out_kernel(const float* __restrict__ w2,
                               const float* __restrict__ b2,
                               float* __restrict__ capO) {
    int warp = threadIdx.x >> 5, lane = threadIdx.x & 31;
    int s = blockIdx.x * 8 + warp;
    float acc[EM];
#pragma unroll
    for (int j = 0; j < EM; j++) acc[j] = 0.f;
    const float* tr = g_t + (size_t)s * DM;
    for (int k = lane; k < DM; k += 32) {
        float tv = tr[k];
#pragma unroll
        for (int j = 0; j < EM; j++) acc[j] += tv * w2[k * EM + j];
    }
#pragma unroll
    for (int j = 0; j < EM; j++) {
#pragma unroll
        for (int o = 16; o > 0; o >>= 1)
            acc[j] += __shfl_xor_sync(0xffffffffu, acc[j], o);
    }
    if (lane == 0) {
#pragma unroll
        for (int j = 0; j < EM; j++) capO[(size_t)s * EM + j] = acc[j] + b2[j];
    }
}

// ---------------- launch -----------------------------------------------------
extern "C" void kernel_launch(void* const* d_in, const int* in_sizes, int n_in,
                              void* d_out, int out_size) {
    const float* x      = (const float*)d_in[0];
    const float* gate_w = (const float*)d_in[1];
    const float* cap_w1 = (const float*)d_in[2];
    const float* cap_b1 = (const float*)d_in[3];
    const float* cap_w2 = (const float*)d_in[4];
    const float* cap_b2 = (const float*)d_in[5];
    const float* exp_w1 = (const float*)d_in[6];
    const float* exp_b1 = (const float*)d_in[7];
    const float* exp_w2 = (const float*)d_in[8];
    const float* exp_b2 = (const float*)d_in[9];

    float* out  = (float*)d_out;
    float* y    = out;                                   // [S, D]
    float* ones = out + (size_t)S_TOK * DM;              // [S, E]
    float* cap  = ones + (size_t)S_TOK * EM;             // [S, E]

    cudaFuncSetAttribute(hgemm<0>, cudaFuncAttributeMaxDynamicSharedMemorySize, SMEM_DYN);
    cudaFuncSetAttribute(hgemm<1>, cudaFuncAttributeMaxDynamicSharedMemorySize, SMEM_DYN);
    cudaFuncSetAttribute(hgemm<2>, cudaFuncAttributeMaxDynamicSharedMemorySize, SMEM_DYN);

    // zero y + ones (cap fully overwritten)
    int n4 = (S_TOK * DM + S_TOK * EM) / 4;
    zero_kernel<<<(n4 + 255) / 256, 256>>>((float4*)out, n4);

    // x -> fp16
    __half* xh; cudaGetSymbolAddress((void**)&xh, g_xh);
    x2h_kernel<<<(S_TOK * DM / 8 + 255) / 256, 256>>>((const float4*)x, (uint2*)xh,
                                                      S_TOK * DM / 8);

    // router softmax scores [E, S]
    gate_softmax_kernel<<<S_TOK / 8, 256>>>(x, gate_w);

    // exact per-expert top-K via radix select (writes gating, idx, ones)
    topk_select_kernel<<<EM, 1024>>>(ones);

    // weight transposes to K-major fp16 (vectorized)
    __half* cw1t; cudaGetSymbolAddress((void**)&cw1t, g_cw1t);
    __half* w1t;  cudaGetSymbolAddress((void**)&w1t, g_w1t);
    __half* w2t;  cudaGetSymbolAddress((void**)&w2t, g_w2t);
    float*  gt;   cudaGetSymbolAddress((void**)&gt, g_t);
    __half* gh;   cudaGetSymbolAddress((void**)&gh, g_h);
    transpose_h_kernel<<<dim3(DM / 64, DM / 64, 1), 256>>>(cap_w1, cw1t, DM, DM);
    transpose_h_kernel<<<dim3(HM / 64, DM / 64, EM), 256>>>(exp_w1, w1t, DM, HM);
    transpose_h_kernel<<<dim3(DM / 64, HM / 64, EM), 256>>>(exp_w2, w2t, HM, DM);

    // capacity predictor: t = silu(x @ cap_w1 + b1); cap = t @ cap_w2 + b2
    hgemm<0><<<dim3(DM / 256, S_TOK / 128, 1), 256, SMEM_DYN>>>(
        xh, cw1t, cap_b1, gt, S_TOK, DM, DM);
    cap_out_kernel<<<S_TOK / 8, 256>>>(cap_w2, cap_b2, cap);

    // expert MLP up-projection: gather + GELU -> fp16 hidden
    hgemm<1><<<dim3(HM / 256, KM / 128, EM), 256, SMEM_DYN>>>(
        xh, w1t, exp_b1, gh, KM, HM, DM);

    // expert MLP down-projection: gating-scale + scatter-add
    hgemm<2><<<dim3(DM / 256, KM / 128, EM), 256, SMEM_DYN>>>(
        gh, w2t, exp_b2, y, KM, DM, HM);
}

// round 7
// speedup vs baseline: 6.3923x; 1.0445x over previous
#include <cuda_runtime.h>
#include <cuda_fp16.h>
#include <cstdint>

// Problem constants
#define S_TOK 8192      // B*S_LEN tokens
#define DM    1024      // model dim
#define EM    8         // experts
#define HM    4096      // hidden
#define KM    2048      // capacity per expert

#define KC        32            // k-chunk (halves)
#define STAGEB    24576         // 8KB A + 16KB B per stage
#define NSTAGE    3
#define SMEM_DYN  (NSTAGE * STAGEB + 1024)

// ---------------- scratch (device globals; no allocation allowed) -----------
__device__ float  g_scores[EM * S_TOK];            // softmaxed router scores [E,S]
__device__ float  g_gating[EM * KM];               // top-K gating values [E,K]
__device__ int    g_idx[EM * KM];                  // top-K token indices [E,K]
__device__ float  g_t[(size_t)S_TOK * DM];         // silu(x@cap_w1+b1) fp32
__device__ __half g_xh[(size_t)S_TOK * DM];        // x in fp16
__device__ __half g_h[(size_t)EM * KM * HM];       // gelu hidden [E,K,H] fp16
__device__ __half g_cw1t[(size_t)DM * DM];         // cap_w1^T fp16
__device__ __half g_w1t[(size_t)EM * HM * DM];     // w1^T per expert [H, D] fp16
__device__ __half g_w2t[(size_t)EM * DM * HM];     // w2^T per expert [D, H] fp16

// ---------------- helpers ----------------------------------------------------
__device__ __forceinline__ float siluf(float v) {
    return v / (1.0f + __expf(-v));
}
__device__ __forceinline__ float geluf(float v) {
    float c = 0.7978845608028654f * (v + 0.044715f * v * v * v);
    return 0.5f * v * (1.0f + tanhf(c));
}
__device__ __forceinline__ void ldm_x4(uint32_t* r, uint32_t addr) {
    asm volatile("ldmatrix.sync.aligned.m8n8.x4.shared.b16 {%0,%1,%2,%3}, [%4];"
                 : "=r"(r[0]), "=r"(r[1]), "=r"(r[2]), "=r"(r[3]) : "r"(addr));
}
__device__ __forceinline__ void mma_f16(float* d, const uint32_t* a, const uint32_t* b) {
    asm volatile(
        "mma.sync.aligned.m16n8k16.row.col.f32.f16.f16.f32 "
        "{%0,%1,%2,%3}, {%4,%5,%6,%7}, {%8,%9}, {%0,%1,%2,%3};"
        : "+f"(d[0]), "+f"(d[1]), "+f"(d[2]), "+f"(d[3])
        : "r"(a[0]), "r"(a[1]), "r"(a[2]), "r"(a[3]), "r"(b[0]), "r"(b[1]));
}
__device__ __forceinline__ void cp16(uint32_t dst, const void* src) {
    asm volatile("cp.async.cg.shared.global [%0], [%1], 16;" :: "r"(dst), "l"(src));
}
__device__ __forceinline__ void cp_commit() {
    asm volatile("cp.async.commit_group;");
}
__device__ __forceinline__ void cp_wait1() {
    asm volatile("cp.async.wait_group 1;");
}
__device__ __forceinline__ uint32_t swzi(uint32_t off) {      // SW128: b[6:4]^=b[9:7]
    return off ^ ((off >> 3) & 0x70);
}

// =================== PREP megakernel: independent small work =================
// roles by blockIdx.x: zero | x2h | softmax | T(cap_w1) | T(exp_w1) | T(exp_w2)
#define ZB   512
#define XB   256
#define SMB  1024
#define T1B  ((DM / 64) * (DM / 64))              // 256
#define T2B  ((HM / 64) * (DM / 64) * EM)         // 8192
#define T3B  ((DM / 64) * (HM / 64) * EM)         // 8192
#define PREP_BLKS (ZB + XB + SMB + T1B + T2B + T3B)

__device__ void transpose64(float* tile /*64*65*/, const float* in,
                            __half* out, int R, int C, int id) {
    const int tx = C / 64;
    const int per = tx * (R / 64);
    const int z = id / per, r2 = id % per;
    const int bx = (r2 % tx) * 64, by = (r2 / tx) * 64;
    in += (size_t)z * R * C;
    out += (size_t)z * R * C;
    const int t = threadIdx.x;
#pragma unroll
    for (int j = 0; j < 4; j++) {
        int i = t + j * 256;
        int r = i >> 4, c4 = (i & 15) * 4;
        float4 v = *(const float4*)(in + (size_t)(by + r) * C + bx + c4);
        tile[r * 65 + c4 + 0] = v.x; tile[r * 65 + c4 + 1] = v.y;
        tile[r * 65 + c4 + 2] = v.z; tile[r * 65 + c4 + 3] = v.w;
    }
    __syncthreads();
#pragma unroll
    for (int j = 0; j < 2; j++) {
        int i = t + j * 256;
        int c = i >> 3, r8 = (i & 7) * 8;
        __half2 p0 = __floats2half2_rn(tile[(r8 + 0) * 65 + c], tile[(r8 + 1) * 65 + c]);
        __half2 p1 = __floats2half2_rn(tile[(r8 + 2) * 65 + c], tile[(r8 + 3) * 65 + c]);
        __half2 p2 = __floats2half2_rn(tile[(r8 + 4) * 65 + c], tile[(r8 + 5) * 65 + c]);
        __half2 p3 = __floats2half2_rn(tile[(r8 + 6) * 65 + c], tile[(r8 + 7) * 65 + c]);
        uint4 pk = make_uint4(*(uint32_t*)&p0, *(uint32_t*)&p1,
                              *(uint32_t*)&p2, *(uint32_t*)&p3);
        *(uint4*)(out + (size_t)(bx + c) * R + by + r8) = pk;
    }
}

__global__ void __launch_bounds__(256)
prep_kernel(const float* __restrict__ x, const float* __restrict__ gw,
            const float* __restrict__ cap_w1, const float* __restrict__ exp_w1,
            const float* __restrict__ exp_w2, float* __restrict__ outzero) {
    __shared__ float tile[64 * 65];
    const int bid = blockIdx.x;
    const int t = threadIdx.x;

    if (bid < ZB) {                                    // zero y + ones
        float4* p = (float4*)outzero;
        const int n4 = (S_TOK * DM + S_TOK * EM) / 4;
        for (int i = bid * 256 + t; i < n4; i += ZB * 256)
            p[i] = make_float4(0.f, 0.f, 0.f, 0.f);
        return;
    }
    if (bid < ZB + XB) {                               // x -> fp16
        const int b = bid - ZB;
        const float4* xi = (const float4*)x;
        uint2* xo = (uint2*)g_xh;
        const int n8 = S_TOK * DM / 8;
        for (int i = b * 256 + t; i < n8; i += XB * 256) {
            float4 a = xi[i * 2], c = xi[i * 2 + 1];
            __half2 h0 = __floats2half2_rn(a.x, a.y);
            __half2 h1 = __floats2half2_rn(a.z, a.w);
            __half2 h2 = __floats2half2_rn(c.x, c.y);
            __half2 h3 = __floats2half2_rn(c.z, c.w);
            xo[i * 2] = make_uint2(*(uint32_t*)&h0, *(uint32_t*)&h1);
            xo[i * 2 + 1] = make_uint2(*(uint32_t*)&h2, *(uint32_t*)&h3);
        }
        return;
    }
    if (bid < ZB + XB + SMB) {                         // router softmax
        const int b = bid - ZB - XB;
        int warp = t >> 5, lane = t & 31;
        int s = b * 8 + warp;
        float acc[EM];
#pragma unroll
        for (int e = 0; e < EM; e++) acc[e] = 0.f;
        const float* xr = x + (size_t)s * DM;
        for (int k = lane; k < DM; k += 32) {
            float xv = xr[k];
#pragma unroll
            for (int e = 0; e < EM; e++) acc[e] += xv * gw[e * DM + k];
        }
#pragma unroll
        for (int e = 0; e < EM; e++) {
#pragma unroll
            for (int o = 16; o > 0; o >>= 1)
                acc[e] += __shfl_xor_sync(0xffffffffu, acc[e], o);
        }
        if (lane == 0) {
            float mx = acc[0];
#pragma unroll
            for (int e = 1; e < EM; e++) mx = fmaxf(mx, acc[e]);
            float sum = 0.f;
#pragma unroll
            for (int e = 0; e < EM; e++) { acc[e] = __expf(acc[e] - mx); sum += acc[e]; }
            float inv = 1.0f / sum;
#pragma unroll
            for (int e = 0; e < EM; e++) g_scores[e * S_TOK + s] = acc[e] * inv;
        }
        return;
    }
    if (bid < ZB + XB + SMB + T1B) {
        transpose64(tile, cap_w1, g_cw1t, DM, DM, bid - ZB - XB - SMB);
        return;
    }
    if (bid < ZB + XB + SMB + T1B + T2B) {
        transpose64(tile, exp_w1, g_w1t, DM, HM, bid - ZB - XB - SMB - T1B);
        return;
    }
    transpose64(tile, exp_w2, g_w2t, HM, DM, bid - ZB - XB - SMB - T1B - T2B);
}

// ============ topk (256-thread, 3-level radix select, exact set) ============
// Same selected SET as jax.lax.top_k (ties -> smallest index); order arbitrary
// (combine is a scatter-add; ones is a set).
__device__ void topk256(char* dyn, int e, float* __restrict__ ones_out) {
    uint32_t* keys = (uint32_t*)dyn;          // 8192
    uint32_t* hist = keys + S_TOK;            // 2048
    uint32_t* tot = hist + 2048;              // 256
    __shared__ uint32_t sb_sel;
    __shared__ int s_pos;
    const int tid = threadIdx.x;

    for (int i = tid; i < S_TOK; i += 256)
        keys[i] = __float_as_uint(g_scores[e * S_TOK + i]);
    if (tid == 0) s_pos = 0;

    uint32_t prefix = 0, prefmask = 0;
    int need = KM;
    const int shifts[3] = {21, 10, 0};
    const int binsN[3] = {2048, 2048, 1024};
    const uint32_t bmask[3] = {2047u, 2047u, 1023u};

#pragma unroll
    for (int lev = 0; lev < 3; lev++) {
        const int nb = binsN[lev];
        const int cpt = nb >> 8;              // bins per thread (8 or 4)
        __syncthreads();
        for (int i = tid; i < nb; i += 256) hist[i] = 0;
        __syncthreads();
        for (int i = tid; i < S_TOK; i += 256) {
            uint32_t k = keys[i];
            if ((k & prefmask) == prefix)
                atomicAdd(&hist[(k >> shifts[lev]) & bmask[lev]], 1u);
        }
        __syncthreads();
        // hierarchical inclusive suffix-sum over hist[0..nb)
        uint32_t loc[8], mySum = 0;
        for (int j = cpt - 1; j >= 0; j--) {
            mySum += hist[tid * cpt + j];
            loc[j] = mySum;
        }
        tot[tid] = mySum;
        __syncthreads();
        for (int off = 1; off < 256; off <<= 1) {
            uint32_t v = tot[tid] + ((tid + off < 256) ? tot[tid + off] : 0u);
            __syncthreads();
            tot[tid] = v;
            __syncthreads();
        }
        uint32_t above = tot[tid] - mySum;     // sum over threads > tid
        for (int j = 0; j < cpt; j++) hist[tid * cpt + j] = loc[j] + above;
        __syncthreads();
        for (int i = tid; i < nb; i += 256) {
            uint32_t s = hist[i];
            uint32_t snx = (i + 1 < nb) ? hist[i + 1] : 0u;
            if (s >= (uint32_t)need && snx < (uint32_t)need) sb_sel = (uint32_t)i;
        }
        __syncthreads();
        uint32_t b = sb_sel;
        uint32_t snx = (b + 1 < (uint32_t)nb) ? hist[b + 1] : 0u;
        need -= (int)snx;
        prefix |= b << shifts[lev];
        prefmask |= bmask[lev] << shifts[lev];
        __syncthreads();
    }

    const uint32_t T = prefix;   // exact K-th value bits
    const int R = need;          // count of == T to take (smallest indices)
    for (int i = tid; i < S_TOK; i += 256) {
        uint32_t k = keys[i];
        bool sel = (k > T);
        if (!sel && k == T) {
            int rank = 0;
            for (int j = 0; j < i; j++)
                if (keys[j] == T) rank++;
            sel = (rank < R);
        }
        if (sel) {
            int p = atomicAdd(&s_pos, 1);
            g_gating[e * KM + p] = __uint_as_float(k);
            g_idx[e * KM + p] = i;
            ones_out[(size_t)i * EM + e] = 1.0f;
        }
    }
}

// ================= GEMM body (device): 128x256 tile, cp.async x3 ============
// MODE 0: g_t = silu(xh @ B^T + bias)            (fp32 out)
// MODE 1: g_h[e] = gelu(gather(xh) @ B^T + bias) (fp16 out)
// MODE 2: y[idx] += gating * (g_h[e] @ B^T + b)  (fp32 atomic out)
template <int MODE>
__device__ void gemm_body(char* dynsmem, const __half* __restrict__ A,
                          const __half* __restrict__ Bw,
                          const float* __restrict__ bias, void* __restrict__ C_,
                          int M, int N, int K, int bx, int by, int e) {
    uint32_t base = (uint32_t)__cvta_generic_to_shared(dynsmem);
    base = (base + 1023u) & ~1023u;

    const int t = threadIdx.x;
    const int lane = t & 31, w = t >> 5;
    const int wm = w & 1, wn = w >> 1;
    const int g = lane >> 2, tg = lane & 3;
    const int row0 = by * 128;
    const int col0 = bx * 256;

    if (MODE == 1) {
        Bw += (size_t)e * N * K;
        bias += (size_t)e * N;
    } else if (MODE == 2) {
        A += (size_t)e * (size_t)M * K;
        Bw += (size_t)e * N * K;
        bias += (size_t)e * N;
    }

    const __half* a_src[2];
    uint32_t a_dst[2];
#pragma unroll
    for (int j = 0; j < 2; j++) {
        int i = t + j * 256;
        int row = i >> 2, u = i & 3;
        a_dst[j] = swzi((uint32_t)(row * 64 + u * 16));
        long arow = row0 + row;
        if (MODE == 1) arow = g_idx[e * KM + arow];
        a_src[j] = A + (size_t)arow * K + u * 8;
    }
    const __half* b_src[4];
    uint32_t b_dst[4];
#pragma unroll
    for (int j = 0; j < 4; j++) {
        int i = t + j * 256;
        int row = i >> 2, u = i & 3;
        b_dst[j] = swzi((uint32_t)(row * 64 + u * 16));
        b_src[j] = Bw + (size_t)(col0 + row) * K + u * 8;
    }

    float acc[4][8][4];
#pragma unroll
    for (int mt = 0; mt < 4; mt++)
#pragma unroll
        for (int nt = 0; nt < 8; nt++)
#pragma unroll
            for (int r = 0; r < 4; r++) acc[mt][nt][r] = 0.f;

    const int NC = K / KC;
#pragma unroll
    for (int st = 0; st < 2; st++) {
        uint32_t ab = base + st * STAGEB;
        uint32_t bb = ab + 8192;
        int kb = st * KC;
#pragma unroll
        for (int j = 0; j < 2; j++) cp16(ab + a_dst[j], a_src[j] + kb);
#pragma unroll
        for (int j = 0; j < 4; j++) cp16(bb + b_dst[j], b_src[j] + kb);
        cp_commit();
    }

    for (int c = 0; c < NC; c++) {
        cp_wait1();
        __syncthreads();
        if (c + 2 < NC) {
            int st = (c + 2) % NSTAGE;
            uint32_t ab = base + st * STAGEB;
            uint32_t bb = ab + 8192;
            int kb = (c + 2) * KC;
#pragma unroll
            for (int j = 0; j < 2; j++) cp16(ab + a_dst[j], a_src[j] + kb);
#pragma unroll
            for (int j = 0; j < 4; j++) cp16(bb + b_dst[j], b_src[j] + kb);
        }
        cp_commit();

        uint32_t sa = base + (c % NSTAGE) * STAGEB;
        uint32_t sb = sa + 8192;
#pragma unroll
        for (int ks = 0; ks < 2; ks++) {
            uint32_t af[4][4], bf[8][2];
            int aunit = (lane >> 4) + ks * 2;
#pragma unroll
            for (int mt = 0; mt < 4; mt++) {
                int r = wm * 64 + mt * 16 + (lane & 15);
                ldm_x4(af[mt], sa + swzi((uint32_t)(r * 64 + aunit * 16)));
            }
            int brow = wn * 64 + ((lane >> 4) << 3) + (lane & 7);
            int bunit = ks * 2 + ((lane >> 3) & 1);
#pragma unroll
            for (int p = 0; p < 4; p++) {
                uint32_t r4[4];
                int r = brow + p * 16;
                ldm_x4(r4, sb + swzi((uint32_t)(r * 64 + bunit * 16)));
                bf[p * 2][0] = r4[0]; bf[p * 2][1] = r4[1];
                bf[p * 2 + 1][0] = r4[2]; bf[p * 2 + 1][1] = r4[3];
            }
#pragma unroll
            for (int mt = 0; mt < 4; mt++)
#pragma unroll
                for (int nt = 0; nt < 8; nt++)
                    mma_f16(acc[mt][nt], af[mt], bf[nt]);
        }
        __syncthreads();
    }

#pragma unroll
    for (int mt = 0; mt < 4; mt++) {
        int r_lo = row0 + wm * 64 + mt * 16 + g;
        int r_hi = r_lo + 8;
        int tok_lo = 0, tok_hi = 0;
        float g_lo = 0.f, g_hi = 0.f;
        if (MODE == 2) {
            tok_lo = g_idx[e * KM + r_lo];
            tok_hi = g_idx[e * KM + r_hi];
            g_lo = g_gating[e * KM + r_lo];
            g_hi = g_gating[e * KM + r_hi];
        }
#pragma unroll
        for (int nt = 0; nt < 8; nt++) {
            int col = col0 + wn * 64 + nt * 8 + 2 * tg;
            float b0 = bias[col], b1 = bias[col + 1];
            float v0 = acc[mt][nt][0] + b0, v1 = acc[mt][nt][1] + b1;
            float v2 = acc[mt][nt][2] + b0, v3 = acc[mt][nt][3] + b1;
            if (MODE == 0) {
                float* Co = (float*)C_;
                *(float2*)(Co + (size_t)r_lo * N + col) = make_float2(siluf(v0), siluf(v1));
                *(float2*)(Co + (size_t)r_hi * N + col) = make_float2(siluf(v2), siluf(v3));
            } else if (MODE == 1) {
                __half* Co = (__half*)C_ + (size_t)e * (size_t)M * N;
                __half2 lo = __floats2half2_rn(geluf(v0), geluf(v1));
                __half2 hi = __floats2half2_rn(geluf(v2), geluf(v3));
                *(__half2*)(Co + (size_t)r_lo * N + col) = lo;
                *(__half2*)(Co + (size_t)r_hi * N + col) = hi;
            } else {
                float* Co = (float*)C_;
                float* ylo = Co + (size_t)tok_lo * DM + col;
                float* yhi = Co + (size_t)tok_hi * DM + col;
                atomicAdd(ylo, g_lo * v0);
                atomicAdd(ylo + 1, g_lo * v1);
                atomicAdd(yhi, g_hi * v2);
                atomicAdd(yhi + 1, g_hi * v3);
            }
        }
    }
}

// ---------- launch 2: topk (8 blocks) || cap GEMM (256 blocks) --------------
__global__ void __launch_bounds__(256, 1)
hgemm0_topk(const __half* __restrict__ A, const __half* __restrict__ Bw,
            const float* __restrict__ bias, float* __restrict__ Cout,
            float* __restrict__ ones_out) {
    extern __shared__ char dynsmem[];
    if (blockIdx.x < 8) {
        topk256(dynsmem, blockIdx.x, ones_out);
        return;
    }
    const int lin = blockIdx.x - 8;
    const int nx = DM / 256;
    gemm_body<0>(dynsmem, A, Bw, bias, Cout, S_TOK, DM, DM,
                 lin % nx, lin / nx, 0);
}

// ---------- launch 3: cap_out (256 blocks) || expert GEMM1 (2048) -----------
__global__ void __launch_bounds__(256, 1)
hgemm1_capout(const __half* __restrict__ A, const __half* __restrict__ Bw,
              const float* __restrict__ bias, __half* __restrict__ Cout,
              const float* __restrict__ cw2, const float* __restrict__ cb2,
              float* __restrict__ capO) {
    extern __shared__ char dynsmem[];
    if (blockIdx.x < 256) {
        // cap = g_t @ cap_w2 + b2 ; 32 tokens per block, warp per token x4
        const int w = threadIdx.x >> 5, lane = threadIdx.x & 31;
#pragma unroll
        for (int q = 0; q < 4; q++) {
            int s = blockIdx.x * 32 + q * 8 + w;
            float acc[EM];
#pragma unroll
            for (int j = 0; j < EM; j++) acc[j] = 0.f;
            const float* tr = g_t + (size_t)s * DM;
            for (int k = lane; k < DM; k += 32) {
                float tv = tr[k];
#pragma unroll
                for (int j = 0; j < EM; j++) acc[j] += tv * cw2[k * EM + j];
            }
#pragma unroll
            for (int j = 0; j < EM; j++) {
#pragma unroll
                for (int o = 16; o > 0; o >>= 1)
                    acc[j] += __shfl_xor_sync(0xffffffffu, acc[j], o);
            }
            if (lane == 0) {
#pragma unroll
                for (int j = 0; j < EM; j++)
                    capO[(size_t)s * EM + j] = acc[j] + cb2[j];
            }
        }
        return;
    }
    const int lin = blockIdx.x - 256;
    const int e = lin >> 8;         // 256 blocks per expert (16x16)
    const int r = lin & 255;
    gemm_body<1>(dynsmem, A, Bw, bias, Cout, KM, HM, DM, r & 15, r >> 4, e);
}

// ---------- launch 4: expert GEMM2 (scatter) ---------------------------------
__global__ void __launch_bounds__(256, 1)
hgemm2(const __half* __restrict__ A, const __half* __restrict__ Bw,
       const float* __restrict__ bias, float* __restrict__ Y) {
    extern __shared__ char dynsmem[];
    gemm_body<2>(dynsmem, A, Bw, bias, Y, KM, DM, HM,
                 blockIdx.x, blockIdx.y, blockIdx.z);
}

// ---------------- launch -----------------------------------------------------
extern "C" void kernel_launch(void* const* d_in, const int* in_sizes, int n_in,
                              void* d_out, int out_size) {
    const float* x      = (const float*)d_in[0];
    const float* gate_w = (const float*)d_in[1];
    const float* cap_w1 = (const float*)d_in[2];
    const float* cap_b1 = (const float*)d_in[3];
    const float* cap_w2 = (const float*)d_in[4];
    const float* cap_b2 = (const float*)d_in[5];
    const float* exp_w1 = (const float*)d_in[6];
    const float* exp_b1 = (const float*)d_in[7];
    const float* exp_w2 = (const float*)d_in[8];
    const float* exp_b2 = (const float*)d_in[9];

    float* out  = (float*)d_out;
    float* y    = out;                                   // [S, D]
    float* ones = out + (size_t)S_TOK * DM;              // [S, E]
    float* cap  = ones + (size_t)S_TOK * EM;             // [S, E]

    cudaFuncSetAttribute(hgemm0_topk, cudaFuncAttributeMaxDynamicSharedMemorySize, SMEM_DYN);
    cudaFuncSetAttribute(hgemm1_capout, cudaFuncAttributeMaxDynamicSharedMemorySize, SMEM_DYN);
    cudaFuncSetAttribute(hgemm2, cudaFuncAttributeMaxDynamicSharedMemorySize, SMEM_DYN);

    __half* xh;   cudaGetSymbolAddress((void**)&xh, g_xh);
    __half* cw1t; cudaGetSymbolAddress((void**)&cw1t, g_cw1t);
    __half* w1t;  cudaGetSymbolAddress((void**)&w1t, g_w1t);
    __half* w2t;  cudaGetSymbolAddress((void**)&w2t, g_w2t);
    float*  gt;   cudaGetSymbolAddress((void**)&gt, g_t);
    __half* gh;   cudaGetSymbolAddress((void**)&gh, g_h);

    // 1: zero + x->fp16 + softmax + all weight transposes (independent)
    prep_kernel<<<PREP_BLKS, 256>>>(x, gate_w, cap_w1, exp_w1, exp_w2, out);

    // 2: topk (8 blocks) || cap GEMM silu (256 blocks)
    hgemm0_topk<<<8 + (DM / 256) * (S_TOK / 128), 256, SMEM_DYN>>>(
        xh, cw1t, cap_b1, gt, ones);

    // 3: cap_out (256 blocks) || expert up-proj GEMM (2048 blocks)
    hgemm1_capout<<<256 + (HM / 256) * (KM / 128) * EM, 256, SMEM_DYN>>>(
        xh, w1t, exp_b1, gh, cap_w2, cap_b2, cap);

    // 4: expert down-proj GEMM + gating scatter-add
    hgemm2<<<dim3(DM / 256, KM / 128, EM), 256, SMEM_DYN>>>(
        gh, w2t, exp_b2, y);
}

// round 8
// speedup vs baseline: 7.7936x; 1.2192x over previous
#include <cuda_runtime.h>
#include <cuda_fp16.h>
#include <cstdint>

// Problem constants
#define S_TOK 8192      // B*S_LEN tokens
#define DM    1024      // model dim
#define EM    8         // experts
#define HM    4096      // hidden
#define KM    2048      // capacity per expert

#define KC        32            // k-chunk (halves)
#define STAGEB    16384         // 8KB A + 8KB B per stage (128x128 tile)
#define NSTAGE    3
#define SMEM_DYN  (NSTAGE * STAGEB + 1024)

// ---------------- scratch (device globals; no allocation allowed) -----------
__device__ float  g_scores[EM * S_TOK];            // softmaxed router scores [E,S]
__device__ float  g_gating[EM * KM];               // top-K gating values [E,K]
__device__ int    g_idx[EM * KM];                  // top-K token indices [E,K]
__device__ float  g_t[(size_t)S_TOK * DM];         // silu(x@cap_w1+b1) fp32
__device__ __half g_xh[(size_t)S_TOK * DM];        // x in fp16
__device__ __half g_h[(size_t)EM * KM * HM];       // gelu hidden [E,K,H] fp16
__device__ __half g_cw1t[(size_t)DM * DM];         // cap_w1^T fp16
__device__ __half g_w1t[(size_t)EM * HM * DM];     // w1^T per expert [H, D] fp16
__device__ __half g_w2t[(size_t)EM * DM * HM];     // w2^T per expert [D, H] fp16

// ---------------- helpers ----------------------------------------------------
__device__ __forceinline__ float siluf(float v) {
    return v / (1.0f + __expf(-v));
}
__device__ __forceinline__ float geluf(float v) {
    float c = 0.7978845608028654f * (v + 0.044715f * v * v * v);
    return 0.5f * v * (1.0f + tanhf(c));
}
__device__ __forceinline__ void ldm_x4(uint32_t* r, uint32_t addr) {
    asm volatile("ldmatrix.sync.aligned.m8n8.x4.shared.b16 {%0,%1,%2,%3}, [%4];"
                 : "=r"(r[0]), "=r"(r[1]), "=r"(r[2]), "=r"(r[3]) : "r"(addr));
}
__device__ __forceinline__ void mma_f16(float* d, const uint32_t* a, const uint32_t* b) {
    asm volatile(
        "mma.sync.aligned.m16n8k16.row.col.f32.f16.f16.f32 "
        "{%0,%1,%2,%3}, {%4,%5,%6,%7}, {%8,%9}, {%0,%1,%2,%3};"
        : "+f"(d[0]), "+f"(d[1]), "+f"(d[2]), "+f"(d[3])
        : "r"(a[0]), "r"(a[1]), "r"(a[2]), "r"(a[3]), "r"(b[0]), "r"(b[1]));
}
__device__ __forceinline__ void cp16(uint32_t dst, const void* src) {
    asm volatile("cp.async.cg.shared.global [%0], [%1], 16;" :: "r"(dst), "l"(src));
}
__device__ __forceinline__ void cp_commit() {
    asm volatile("cp.async.commit_group;");
}
__device__ __forceinline__ void cp_wait1() {
    asm volatile("cp.async.wait_group 1;");
}
__device__ __forceinline__ uint32_t swzi(uint32_t off) {      // SW128: b[6:4]^=b[9:7]
    return off ^ ((off >> 3) & 0x70);
}

// =================== PREP megakernel: independent small work =================
#define ZB   512
#define XB   256
#define SMB  1024
#define T1B  ((DM / 64) * (DM / 64))              // 256
#define T2B  ((HM / 64) * (DM / 64) * EM)         // 8192
#define T3B  ((DM / 64) * (HM / 64) * EM)         // 8192
#define PREP_BLKS (ZB + XB + SMB + T1B + T2B + T3B)

__device__ void transpose64(float* tile /*64*65*/, const float* in,
                            __half* out, int R, int C, int id) {
    const int tx = C / 64;
    const int per = tx * (R / 64);
    const int z = id / per, r2 = id % per;
    const int bx = (r2 % tx) * 64, by = (r2 / tx) * 64;
    in += (size_t)z * R * C;
    out += (size_t)z * R * C;
    const int t = threadIdx.x;
#pragma unroll
    for (int j = 0; j < 4; j++) {
        int i = t + j * 256;
        int r = i >> 4, c4 = (i & 15) * 4;
        float4 v = *(const float4*)(in + (size_t)(by + r) * C + bx + c4);
        tile[r * 65 + c4 + 0] = v.x; tile[r * 65 + c4 + 1] = v.y;
        tile[r * 65 + c4 + 2] = v.z; tile[r * 65 + c4 + 3] = v.w;
    }
    __syncthreads();
#pragma unroll
    for (int j = 0; j < 2; j++) {
        int i = t + j * 256;
        int c = i >> 3, r8 = (i & 7) * 8;
        __half2 p0 = __floats2half2_rn(tile[(r8 + 0) * 65 + c], tile[(r8 + 1) * 65 + c]);
        __half2 p1 = __floats2half2_rn(tile[(r8 + 2) * 65 + c], tile[(r8 + 3) * 65 + c]);
        __half2 p2 = __floats2half2_rn(tile[(r8 + 4) * 65 + c], tile[(r8 + 5) * 65 + c]);
        __half2 p3 = __floats2half2_rn(tile[(r8 + 6) * 65 + c], tile[(r8 + 7) * 65 + c]);
        uint4 pk = make_uint4(*(uint32_t*)&p0, *(uint32_t*)&p1,
                              *(uint32_t*)&p2, *(uint32_t*)&p3);
        *(uint4*)(out + (size_t)(bx + c) * R + by + r8) = pk;
    }
}

__global__ void __launch_bounds__(256)
prep_kernel(const float* __restrict__ x, const float* __restrict__ gw,
            const float* __restrict__ cap_w1, const float* __restrict__ exp_w1,
            const float* __restrict__ exp_w2, float* __restrict__ outzero) {
    __shared__ float tile[64 * 65];
    const int bid = blockIdx.x;
    const int t = threadIdx.x;

    if (bid < ZB) {
        float4* p = (float4*)outzero;
        const int n4 = (S_TOK * DM + S_TOK * EM) / 4;
        for (int i = bid * 256 + t; i < n4; i += ZB * 256)
            p[i] = make_float4(0.f, 0.f, 0.f, 0.f);
        return;
    }
    if (bid < ZB + XB) {
        const int b = bid - ZB;
        const float4* xi = (const float4*)x;
        uint2* xo = (uint2*)g_xh;
        const int n8 = S_TOK * DM / 8;
        for (int i = b * 256 + t; i < n8; i += XB * 256) {
            float4 a = xi[i * 2], c = xi[i * 2 + 1];
            __half2 h0 = __floats2half2_rn(a.x, a.y);
            __half2 h1 = __floats2half2_rn(a.z, a.w);
            __half2 h2 = __floats2half2_rn(c.x, c.y);
            __half2 h3 = __floats2half2_rn(c.z, c.w);
            xo[i * 2] = make_uint2(*(uint32_t*)&h0, *(uint32_t*)&h1);
            xo[i * 2 + 1] = make_uint2(*(uint32_t*)&h2, *(uint32_t*)&h3);
        }
        return;
    }
    if (bid < ZB + XB + SMB) {
        const int b = bid - ZB - XB;
        int warp = t >> 5, lane = t & 31;
        int s = b * 8 + warp;
        float acc[EM];
#pragma unroll
        for (int e = 0; e < EM; e++) acc[e] = 0.f;
        const float* xr = x + (size_t)s * DM;
        for (int k = lane; k < DM; k += 32) {
            float xv = xr[k];
#pragma unroll
            for (int e = 0; e < EM; e++) acc[e] += xv * gw[e * DM + k];
        }
#pragma unroll
        for (int e = 0; e < EM; e++) {
#pragma unroll
            for (int o = 16; o > 0; o >>= 1)
                acc[e] += __shfl_xor_sync(0xffffffffu, acc[e], o);
        }
        if (lane == 0) {
            float mx = acc[0];
#pragma unroll
            for (int e = 1; e < EM; e++) mx = fmaxf(mx, acc[e]);
            float sum = 0.f;
#pragma unroll
            for (int e = 0; e < EM; e++) { acc[e] = __expf(acc[e] - mx); sum += acc[e]; }
            float inv = 1.0f / sum;
#pragma unroll
            for (int e = 0; e < EM; e++) g_scores[e * S_TOK + s] = acc[e] * inv;
        }
        return;
    }
    if (bid < ZB + XB + SMB + T1B) {
        transpose64(tile, cap_w1, g_cw1t, DM, DM, bid - ZB - XB - SMB);
        return;
    }
    if (bid < ZB + XB + SMB + T1B + T2B) {
        transpose64(tile, exp_w1, g_w1t, DM, HM, bid - ZB - XB - SMB - T1B);
        return;
    }
    transpose64(tile, exp_w2, g_w2t, HM, DM, bid - ZB - XB - SMB - T1B - T2B);
}

// ============ topk (128-thread, 3-level radix select, exact set) ============
__device__ void topk128(char* dyn, int e, float* __restrict__ ones_out) {
    uint32_t* keys = (uint32_t*)dyn;          // 8192 words
    uint32_t* hist = keys + S_TOK;            // 2048
    uint32_t* tot = hist + 2048;              // 128
    __shared__ uint32_t sb_sel;
    __shared__ int s_pos;
    const int tid = threadIdx.x;              // 128 threads

    for (int i = tid; i < S_TOK; i += 128)
        keys[i] = __float_as_uint(g_scores[e * S_TOK + i]);
    if (tid == 0) s_pos = 0;

    uint32_t prefix = 0, prefmask = 0;
    int need = KM;
    const int shifts[3] = {21, 10, 0};
    const int binsN[3] = {2048, 2048, 1024};
    const uint32_t bmask[3] = {2047u, 2047u, 1023u};

#pragma unroll
    for (int lev = 0; lev < 3; lev++) {
        const int nb = binsN[lev];
        const int cpt = nb >> 7;              // bins per thread (16 or 8)
        __syncthreads();
        for (int i = tid; i < nb; i += 128) hist[i] = 0;
        __syncthreads();
        for (int i = tid; i < S_TOK; i += 128) {
            uint32_t k = keys[i];
            if ((k & prefmask) == prefix)
                atomicAdd(&hist[(k >> shifts[lev]) & bmask[lev]], 1u);
        }
        __syncthreads();
        uint32_t loc[16], mySum = 0;
        for (int j = cpt - 1; j >= 0; j--) {
            mySum += hist[tid * cpt + j];
            loc[j] = mySum;
        }
        tot[tid] = mySum;
        __syncthreads();
        for (int off = 1; off < 128; off <<= 1) {
            uint32_t v = tot[tid] + ((tid + off < 128) ? tot[tid + off] : 0u);
            __syncthreads();
            tot[tid] = v;
            __syncthreads();
        }
        uint32_t above = tot[tid] - mySum;
        for (int j = 0; j < cpt; j++) hist[tid * cpt + j] = loc[j] + above;
        __syncthreads();
        for (int i = tid; i < nb; i += 128) {
            uint32_t s = hist[i];
            uint32_t snx = (i + 1 < nb) ? hist[i + 1] : 0u;
            if (s >= (uint32_t)need && snx < (uint32_t)need) sb_sel = (uint32_t)i;
        }
        __syncthreads();
        uint32_t b = sb_sel;
        uint32_t snx = (b + 1 < (uint32_t)nb) ? hist[b + 1] : 0u;
        need -= (int)snx;
        prefix |= b << shifts[lev];
        prefmask |= bmask[lev] << shifts[lev];
        __syncthreads();
    }

    const uint32_t T = prefix;
    const int R = need;
    for (int i = tid; i < S_TOK; i += 128) {
        uint32_t k = keys[i];
        bool sel = (k > T);
        if (!sel && k == T) {
            int rank = 0;
            for (int j = 0; j < i; j++)
                if (keys[j] == T) rank++;
            sel = (rank < R);
        }
        if (sel) {
            int p = atomicAdd(&s_pos, 1);
            g_gating[e * KM + p] = __uint_as_float(k);
            g_idx[e * KM + p] = i;
            ones_out[(size_t)i * EM + e] = 1.0f;
        }
    }
}

// ====== GEMM body: 128-thread CTA, 128x128 tile, warp 64x64, cp.async x3 ====
// MODE 0: g_t = silu(xh @ B^T + bias)            (fp32 out)
// MODE 1: g_h[e] = gelu(gather(xh) @ B^T + bias) (fp16 out)
// MODE 2: y[idx] += gating * (g_h[e] @ B^T + b)  (fp32 atomic out)
template <int MODE>
__device__ void gemm_body(char* dynsmem, const __half* __restrict__ A,
                          const __half* __restrict__ Bw,
                          const float* __restrict__ bias, void* __restrict__ C_,
                          int M, int N, int K, int bx, int by, int e) {
    uint32_t base = (uint32_t)__cvta_generic_to_shared(dynsmem);
    base = (base + 1023u) & ~1023u;

    const int t = threadIdx.x;                 // 128 threads, 4 warps
    const int lane = t & 31, w = t >> 5;
    const int wm = w & 1, wn = w >> 1;         // warp tile: rows wm*64, cols wn*64
    const int g = lane >> 2, tg = lane & 3;
    const int row0 = by * 128;
    const int col0 = bx * 128;

    if (MODE == 1) {
        Bw += (size_t)e * N * K;
        bias += (size_t)e * N;
    } else if (MODE == 2) {
        A += (size_t)e * (size_t)M * K;
        Bw += (size_t)e * N * K;
        bias += (size_t)e * N;
    }

    // loaders: A tile 128x32 halves = 512 16B units, 4/thread; B same
    const __half* a_src[4];
    const __half* b_src[4];
    uint32_t ab_dst[4];
#pragma unroll
    for (int j = 0; j < 4; j++) {
        int i = t + j * 128;
        int row = i >> 2, u = i & 3;
        ab_dst[j] = swzi((uint32_t)(row * 64 + u * 16));
        long arow = row0 + row;
        if (MODE == 1) arow = g_idx[e * KM + arow];
        a_src[j] = A + (size_t)arow * K + u * 8;
        b_src[j] = Bw + (size_t)(col0 + row) * K + u * 8;
    }

    float acc[4][8][4];
#pragma unroll
    for (int mt = 0; mt < 4; mt++)
#pragma unroll
        for (int nt = 0; nt < 8; nt++)
#pragma unroll
            for (int r = 0; r < 4; r++) acc[mt][nt][r] = 0.f;

    const int NC = K / KC;
#pragma unroll
    for (int st = 0; st < 2; st++) {
        uint32_t ab = base + st * STAGEB;
        uint32_t bb = ab + 8192;
        int kb = st * KC;
#pragma unroll
        for (int j = 0; j < 4; j++) cp16(ab + ab_dst[j], a_src[j] + kb);
#pragma unroll
        for (int j = 0; j < 4; j++) cp16(bb + ab_dst[j], b_src[j] + kb);
        cp_commit();
    }

    for (int c = 0; c < NC; c++) {
        cp_wait1();
        __syncthreads();
        if (c + 2 < NC) {
            int st = (c + 2) % NSTAGE;
            uint32_t ab = base + st * STAGEB;
            uint32_t bb = ab + 8192;
            int kb = (c + 2) * KC;
#pragma unroll
            for (int j = 0; j < 4; j++) cp16(ab + ab_dst[j], a_src[j] + kb);
#pragma unroll
            for (int j = 0; j < 4; j++) cp16(bb + ab_dst[j], b_src[j] + kb);
        }
        cp_commit();

        uint32_t sa = base + (c % NSTAGE) * STAGEB;
        uint32_t sb = sa + 8192;
#pragma unroll
        for (int ks = 0; ks < 2; ks++) {
            uint32_t af[4][4], bf[8][2];
            int aunit = (lane >> 4) + ks * 2;
#pragma unroll
            for (int mt = 0; mt < 4; mt++) {
                int r = wm * 64 + mt * 16 + (lane & 15);
                ldm_x4(af[mt], sa + swzi((uint32_t)(r * 64 + aunit * 16)));
            }
            int brow = wn * 64 + ((lane >> 4) << 3) + (lane & 7);
            int bunit = ks * 2 + ((lane >> 3) & 1);
#pragma unroll
            for (int p = 0; p < 4; p++) {
                uint32_t r4[4];
                int r = brow + p * 16;
                ldm_x4(r4, sb + swzi((uint32_t)(r * 64 + bunit * 16)));
                bf[p * 2][0] = r4[0]; bf[p * 2][1] = r4[1];
                bf[p * 2 + 1][0] = r4[2]; bf[p * 2 + 1][1] = r4[3];
            }
#pragma unroll
            for (int mt = 0; mt < 4; mt++)
#pragma unroll
                for (int nt = 0; nt < 8; nt++)
                    mma_f16(acc[mt][nt], af[mt], bf[nt]);
        }
        __syncthreads();
    }

#pragma unroll
    for (int mt = 0; mt < 4; mt++) {
        int r_lo = row0 + wm * 64 + mt * 16 + g;
        int r_hi = r_lo + 8;
        int tok_lo = 0, tok_hi = 0;
        float g_lo = 0.f, g_hi = 0.f;
        if (MODE == 2) {
            tok_lo = g_idx[e * KM + r_lo];
            tok_hi = g_idx[e * KM + r_hi];
            g_lo = g_gating[e * KM + r_lo];
            g_hi = g_gating[e * KM + r_hi];
        }
#pragma unroll
        for (int nt = 0; nt < 8; nt++) {
            int col = col0 + wn * 64 + nt * 8 + 2 * tg;
            float b0 = bias[col], b1 = bias[col + 1];
            float v0 = acc[mt][nt][0] + b0, v1 = acc[mt][nt][1] + b1;
            float v2 = acc[mt][nt][2] + b0, v3 = acc[mt][nt][3] + b1;
            if (MODE == 0) {
                float* Co = (float*)C_;
                *(float2*)(Co + (size_t)r_lo * N + col) = make_float2(siluf(v0), siluf(v1));
                *(float2*)(Co + (size_t)r_hi * N + col) = make_float2(siluf(v2), siluf(v3));
            } else if (MODE == 1) {
                __half* Co = (__half*)C_ + (size_t)e * (size_t)M * N;
                __half2 lo = __floats2half2_rn(geluf(v0), geluf(v1));
                __half2 hi = __floats2half2_rn(geluf(v2), geluf(v3));
                *(__half2*)(Co + (size_t)r_lo * N + col) = lo;
                *(__half2*)(Co + (size_t)r_hi * N + col) = hi;
            } else {
                float* Co = (float*)C_;
                float* ylo = Co + (size_t)tok_lo * DM + col;
                float* yhi = Co + (size_t)tok_hi * DM + col;
                atomicAdd(ylo, g_lo * v0);
                atomicAdd(ylo + 1, g_lo * v1);
                atomicAdd(yhi, g_hi * v2);
                atomicAdd(yhi + 1, g_hi * v3);
            }
        }
    }
}

// ---------- launch 2: topk (8 blocks) || cap GEMM (512 blocks) --------------
__global__ void __launch_bounds__(128, 2)
hgemm0_topk(const __half* __restrict__ A, const __half* __restrict__ Bw,
            const float* __restrict__ bias, float* __restrict__ Cout,
            float* __restrict__ ones_out) {
    extern __shared__ char dynsmem[];
    if (blockIdx.x < 8) {
        topk128(dynsmem, blockIdx.x, ones_out);
        return;
    }
    const int lin = blockIdx.x - 8;
    const int nx = DM / 128;
    gemm_body<0>(dynsmem, A, Bw, bias, Cout, S_TOK, DM, DM,
                 lin % nx, lin / nx, 0);
}

// ---------- launch 3: cap_out (256 blocks) || expert GEMM1 (4096) -----------
__global__ void __launch_bounds__(128, 2)
hgemm1_capout(const __half* __restrict__ A, const __half* __restrict__ Bw,
              const float* __restrict__ bias, __half* __restrict__ Cout,
              const float* __restrict__ cw2, const float* __restrict__ cb2,
              float* __restrict__ capO) {
    extern __shared__ char dynsmem[];
    if (blockIdx.x < 256) {
        const int w = threadIdx.x >> 5, lane = threadIdx.x & 31;
#pragma unroll
        for (int q = 0; q < 8; q++) {
            int s = blockIdx.x * 32 + q * 4 + w;
            float acc[EM];
#pragma unroll
            for (int j = 0; j < EM; j++) acc[j] = 0.f;
            const float* tr = g_t + (size_t)s * DM;
            for (int k = lane; k < DM; k += 32) {
                float tv = tr[k];
#pragma unroll
                for (int j = 0; j < EM; j++) acc[j] += tv * cw2[k * EM + j];
            }
#pragma unroll
            for (int j = 0; j < EM; j++) {
#pragma unroll
                for (int o = 16; o > 0; o >>= 1)
                    acc[j] += __shfl_xor_sync(0xffffffffu, acc[j], o);
            }
            if (lane == 0) {
#pragma unroll
                for (int j = 0; j < EM; j++)
                    capO[(size_t)s * EM + j] = acc[j] + cb2[j];
            }
        }
        return;
    }
    const int lin = blockIdx.x - 256;
    const int e = lin >> 9;         // 512 blocks per expert (32x16)
    const int r = lin & 511;
    gemm_body<1>(dynsmem, A, Bw, bias, Cout, KM, HM, DM, r & 31, r >> 5, e);
}

// ---------- launch 4: expert GEMM2 (scatter) ---------------------------------
__global__ void __launch_bounds__(128, 2)
hgemm2(const __half* __restrict__ A, const __half* __restrict__ Bw,
       const float* __restrict__ bias, float* __restrict__ Y) {
    extern __shared__ char dynsmem[];
    gemm_body<2>(dynsmem, A, Bw, bias, Y, KM, DM, HM,
                 blockIdx.x, blockIdx.y, blockIdx.z);
}

// ---------------- launch -----------------------------------------------------
extern "C" void kernel_launch(void* const* d_in, const int* in_sizes, int n_in,
                              void* d_out, int out_size) {
    const float* x      = (const float*)d_in[0];
    const float* gate_w = (const float*)d_in[1];
    const float* cap_w1 = (const float*)d_in[2];
    const float* cap_b1 = (const float*)d_in[3];
    const float* cap_w2 = (const float*)d_in[4];
    const float* cap_b2 = (const float*)d_in[5];
    const float* exp_w1 = (const float*)d_in[6];
    const float* exp_b1 = (const float*)d_in[7];
    const float* exp_w2 = (const float*)d_in[8];
    const float* exp_b2 = (const float*)d_in[9];

    float* out  = (float*)d_out;
    float* y    = out;                                   // [S, D]
    float* ones = out + (size_t)S_TOK * DM;              // [S, E]
    float* cap  = ones + (size_t)S_TOK * EM;             // [S, E]

    cudaFuncSetAttribute(hgemm0_topk, cudaFuncAttributeMaxDynamicSharedMemorySize, SMEM_DYN);
    cudaFuncSetAttribute(hgemm1_capout, cudaFuncAttributeMaxDynamicSharedMemorySize, SMEM_DYN);
    cudaFuncSetAttribute(hgemm2, cudaFuncAttributeMaxDynamicSharedMemorySize, SMEM_DYN);

    __half* xh;   cudaGetSymbolAddress((void**)&xh, g_xh);
    __half* cw1t; cudaGetSymbolAddress((void**)&cw1t, g_cw1t);
    __half* w1t;  cudaGetSymbolAddress((void**)&w1t, g_w1t);
    __half* w2t;  cudaGetSymbolAddress((void**)&w2t, g_w2t);
    float*  gt;   cudaGetSymbolAddress((void**)&gt, g_t);
    __half* gh;   cudaGetSymbolAddress((void**)&gh, g_h);

    // 1: zero + x->fp16 + softmax + all weight transposes (independent)
    prep_kernel<<<PREP_BLKS, 256>>>(x, gate_w, cap_w1, exp_w1, exp_w2, out);

    // 2: topk (8 blocks) || cap GEMM silu (512 blocks)
    hgemm0_topk<<<8 + (DM / 128) * (S_TOK / 128), 128, SMEM_DYN>>>(
        xh, cw1t, cap_b1, gt, ones);

    // 3: cap_out (256 blocks) || expert up-proj GEMM (4096 blocks)
    hgemm1_capout<<<256 + (HM / 128) * (KM / 128) * EM, 128, SMEM_DYN>>>(
        xh, w1t, exp_b1, gh, cap_w2, cap_b2, cap);

    // 4: expert down-proj GEMM + gating scatter-add
    hgemm2<<<dim3(DM / 128, KM / 128, EM), 128, SMEM_DYN>>>(
        gh, w2t, exp_b2, y);
}

// round 9
// speedup vs baseline: 7.9599x; 1.0213x over previous
#include <cuda_runtime.h>
#include <cuda_fp16.h>
#include <cstdint>

// Problem constants
#define S_TOK 8192      // B*S_LEN tokens
#define DM    1024      // model dim
#define EM    8         // experts
#define HM    4096      // hidden
#define KM    2048      // capacity per expert

#define KC        32            // k-chunk (halves)
#define STAGEB    16384         // 8KB A + 8KB B per stage (128x128 tile)
#define NSTAGE    4
#define SMEM_DYN  (NSTAGE * STAGEB + 1024)

// ---------------- scratch (device globals; no allocation allowed) -----------
__device__ float  g_scores[EM * S_TOK];            // softmaxed router scores [E,S]
__device__ float  g_gating[EM * KM];               // top-K gating values [E,K]
__device__ int    g_idx[EM * KM];                  // top-K token indices [E,K]
__device__ float  g_t[(size_t)S_TOK * DM];         // silu(x@cap_w1+b1) fp32
__device__ __half g_xh[(size_t)S_TOK * DM];        // x in fp16
__device__ __half g_h[(size_t)EM * KM * HM];       // gelu hidden [E,K,H] fp16
__device__ __half g_cw1t[(size_t)DM * DM];         // cap_w1^T fp16
__device__ __half g_w1t[(size_t)EM * HM * DM];     // w1^T per expert [H, D] fp16
__device__ __half g_w2t[(size_t)EM * DM * HM];     // w2^T per expert [D, H] fp16

// ---------------- helpers ----------------------------------------------------
__device__ __forceinline__ float siluf(float v) {
    return v / (1.0f + __expf(-v));
}
__device__ __forceinline__ float geluf(float v) {
    float c = 0.7978845608028654f * (v + 0.044715f * v * v * v);
    return 0.5f * v * (1.0f + tanhf(c));
}
__device__ __forceinline__ void ldm_x4(uint32_t* r, uint32_t addr) {
    asm volatile("ldmatrix.sync.aligned.m8n8.x4.shared.b16 {%0,%1,%2,%3}, [%4];"
                 : "=r"(r[0]), "=r"(r[1]), "=r"(r[2]), "=r"(r[3]) : "r"(addr));
}
__device__ __forceinline__ void mma_f16(float* d, const uint32_t* a, const uint32_t* b) {
    asm volatile(
        "mma.sync.aligned.m16n8k16.row.col.f32.f16.f16.f32 "
        "{%0,%1,%2,%3}, {%4,%5,%6,%7}, {%8,%9}, {%0,%1,%2,%3};"
        : "+f"(d[0]), "+f"(d[1]), "+f"(d[2]), "+f"(d[3])
        : "r"(a[0]), "r"(a[1]), "r"(a[2]), "r"(a[3]), "r"(b[0]), "r"(b[1]));
}
__device__ __forceinline__ void cp16(uint32_t dst, const void* src) {
    asm volatile("cp.async.cg.shared.global [%0], [%1], 16;" :: "r"(dst), "l"(src));
}
__device__ __forceinline__ void cp_commit() {
    asm volatile("cp.async.commit_group;");
}
__device__ __forceinline__ void cp_wait2() {
    asm volatile("cp.async.wait_group 2;");
}
__device__ __forceinline__ uint32_t swzi(uint32_t off) {      // SW128: b[6:4]^=b[9:7]
    return off ^ ((off >> 3) & 0x70);
}

// ------------- transpose64: 128-thread, tile from dynamic smem --------------
__device__ void transpose64_128(float* tile /*64*65*/, const float* in,
                                __half* out, int R, int C, int id) {
    const int tx = C / 64;
    const int per = tx * (R / 64);
    const int z = id / per, r2 = id % per;
    const int bx = (r2 % tx) * 64, by = (r2 / tx) * 64;
    in += (size_t)z * R * C;
    out += (size_t)z * R * C;
    const int t = threadIdx.x;          // 128 threads
#pragma unroll
    for (int j = 0; j < 8; j++) {
        int i = t + j * 128;
        int r = i >> 4, c4 = (i & 15) * 4;
        float4 v = *(const float4*)(in + (size_t)(by + r) * C + bx + c4);
        tile[r * 65 + c4 + 0] = v.x; tile[r * 65 + c4 + 1] = v.y;
        tile[r * 65 + c4 + 2] = v.z; tile[r * 65 + c4 + 3] = v.w;
    }
    __syncthreads();
#pragma unroll
    for (int j = 0; j < 4; j++) {
        int i = t + j * 128;
        int c = i >> 3, r8 = (i & 7) * 8;
        __half2 p0 = __floats2half2_rn(tile[(r8 + 0) * 65 + c], tile[(r8 + 1) * 65 + c]);
        __half2 p1 = __floats2half2_rn(tile[(r8 + 2) * 65 + c], tile[(r8 + 3) * 65 + c]);
        __half2 p2 = __floats2half2_rn(tile[(r8 + 4) * 65 + c], tile[(r8 + 5) * 65 + c]);
        __half2 p3 = __floats2half2_rn(tile[(r8 + 6) * 65 + c], tile[(r8 + 7) * 65 + c]);
        uint4 pk = make_uint4(*(uint32_t*)&p0, *(uint32_t*)&p1,
                              *(uint32_t*)&p2, *(uint32_t*)&p3);
        *(uint4*)(out + (size_t)(bx + c) * R + by + r8) = pk;
    }
}

// =================== PREP: zero | x2h | softmax | T(cap_w1) =================
#define ZB   512
#define XB   256
#define SMB  1024
#define T1B  ((DM / 64) * (DM / 64))              // 256
#define PREP_BLKS (ZB + XB + SMB + T1B)

__global__ void __launch_bounds__(256)
prep_kernel(const float* __restrict__ x, const float* __restrict__ gw,
            const float* __restrict__ cap_w1, float* __restrict__ outzero) {
    __shared__ float tile[64 * 65];
    const int bid = blockIdx.x;
    const int t = threadIdx.x;

    if (bid < ZB) {
        float4* p = (float4*)outzero;
        const int n4 = (S_TOK * DM + S_TOK * EM) / 4;
        for (int i = bid * 256 + t; i < n4; i += ZB * 256)
            p[i] = make_float4(0.f, 0.f, 0.f, 0.f);
        return;
    }
    if (bid < ZB + XB) {
        const int b = bid - ZB;
        const float4* xi = (const float4*)x;
        uint2* xo = (uint2*)g_xh;
        const int n8 = S_TOK * DM / 8;
        for (int i = b * 256 + t; i < n8; i += XB * 256) {
            float4 a = xi[i * 2], c = xi[i * 2 + 1];
            __half2 h0 = __floats2half2_rn(a.x, a.y);
            __half2 h1 = __floats2half2_rn(a.z, a.w);
            __half2 h2 = __floats2half2_rn(c.x, c.y);
            __half2 h3 = __floats2half2_rn(c.z, c.w);
            xo[i * 2] = make_uint2(*(uint32_t*)&h0, *(uint32_t*)&h1);
            xo[i * 2 + 1] = make_uint2(*(uint32_t*)&h2, *(uint32_t*)&h3);
        }
        return;
    }
    if (bid < ZB + XB + SMB) {
        const int b = bid - ZB - XB;
        int warp = t >> 5, lane = t & 31;
        int s = b * 8 + warp;
        float acc[EM];
#pragma unroll
        for (int e = 0; e < EM; e++) acc[e] = 0.f;
        const float* xr = x + (size_t)s * DM;
        for (int k = lane; k < DM; k += 32) {
            float xv = xr[k];
#pragma unroll
            for (int e = 0; e < EM; e++) acc[e] += xv * gw[e * DM + k];
        }
#pragma unroll
        for (int e = 0; e < EM; e++) {
#pragma unroll
            for (int o = 16; o > 0; o >>= 1)
                acc[e] += __shfl_xor_sync(0xffffffffu, acc[e], o);
        }
        if (lane == 0) {
            float mx = acc[0];
#pragma unroll
            for (int e = 1; e < EM; e++) mx = fmaxf(mx, acc[e]);
            float sum = 0.f;
#pragma unroll
            for (int e = 0; e < EM; e++) { acc[e] = __expf(acc[e] - mx); sum += acc[e]; }
            float inv = 1.0f / sum;
#pragma unroll
            for (int e = 0; e < EM; e++) g_scores[e * S_TOK + s] = acc[e] * inv;
        }
        return;
    }
    // T(cap_w1) with 256 threads: reuse 128-thread body twice per loop trip
    {
        const int id = bid - ZB - XB - SMB;
        const int bx = (id % (DM / 64)) * 64, by = (id / (DM / 64)) * 64;
#pragma unroll
        for (int j = 0; j < 4; j++) {
            int i = t + j * 256;
            int r = i >> 4, c4 = (i & 15) * 4;
            float4 v = *(const float4*)(cap_w1 + (size_t)(by + r) * DM + bx + c4);
            tile[r * 65 + c4 + 0] = v.x; tile[r * 65 + c4 + 1] = v.y;
            tile[r * 65 + c4 + 2] = v.z; tile[r * 65 + c4 + 3] = v.w;
        }
        __syncthreads();
#pragma unroll
        for (int j = 0; j < 2; j++) {
            int i = t + j * 256;
            int c = i >> 3, r8 = (i & 7) * 8;
            __half2 p0 = __floats2half2_rn(tile[(r8 + 0) * 65 + c], tile[(r8 + 1) * 65 + c]);
            __half2 p1 = __floats2half2_rn(tile[(r8 + 2) * 65 + c], tile[(r8 + 3) * 65 + c]);
            __half2 p2 = __floats2half2_rn(tile[(r8 + 4) * 65 + c], tile[(r8 + 5) * 65 + c]);
            __half2 p3 = __floats2half2_rn(tile[(r8 + 6) * 65 + c], tile[(r8 + 7) * 65 + c]);
            uint4 pk = make_uint4(*(uint32_t*)&p0, *(uint32_t*)&p1,
                                  *(uint32_t*)&p2, *(uint32_t*)&p3);
            *(uint4*)(g_cw1t + (size_t)(bx + c) * DM + by + r8) = pk;
        }
    }
}

// ============ topk (128-thread, 3-level radix select, exact set) ============
__device__ void topk128(char* dyn, int e, float* __restrict__ ones_out) {
    uint32_t* keys = (uint32_t*)dyn;          // 8192 words
    uint32_t* hist = keys + S_TOK;            // 2048
    uint32_t* tot = hist + 2048;              // 128
    __shared__ uint32_t sb_sel;
    __shared__ int s_pos;
    const int tid = threadIdx.x;              // 128 threads

    for (int i = tid; i < S_TOK; i += 128)
        keys[i] = __float_as_uint(g_scores[e * S_TOK + i]);
    if (tid == 0) s_pos = 0;

    uint32_t prefix = 0, prefmask = 0;
    int need = KM;
    const int shifts[3] = {21, 10, 0};
    const int binsN[3] = {2048, 2048, 1024};
    const uint32_t bmask[3] = {2047u, 2047u, 1023u};

#pragma unroll
    for (int lev = 0; lev < 3; lev++) {
        const int nb = binsN[lev];
        const int cpt = nb >> 7;
        __syncthreads();
        for (int i = tid; i < nb; i += 128) hist[i] = 0;
        __syncthreads();
        for (int i = tid; i < S_TOK; i += 128) {
            uint32_t k = keys[i];
            if ((k & prefmask) == prefix)
                atomicAdd(&hist[(k >> shifts[lev]) & bmask[lev]], 1u);
        }
        __syncthreads();
        uint32_t loc[16], mySum = 0;
        for (int j = cpt - 1; j >= 0; j--) {
            mySum += hist[tid * cpt + j];
            loc[j] = mySum;
        }
        tot[tid] = mySum;
        __syncthreads();
        for (int off = 1; off < 128; off <<= 1) {
            uint32_t v = tot[tid] + ((tid + off < 128) ? tot[tid + off] : 0u);
            __syncthreads();
            tot[tid] = v;
            __syncthreads();
        }
        uint32_t above = tot[tid] - mySum;
        for (int j = 0; j < cpt; j++) hist[tid * cpt + j] = loc[j] + above;
        __syncthreads();
        for (int i = tid; i < nb; i += 128) {
            uint32_t s = hist[i];
            uint32_t snx = (i + 1 < nb) ? hist[i + 1] : 0u;
            if (s >= (uint32_t)need && snx < (uint32_t)need) sb_sel = (uint32_t)i;
        }
        __syncthreads();
        uint32_t b = sb_sel;
        uint32_t snx = (b + 1 < (uint32_t)nb) ? hist[b + 1] : 0u;
        need -= (int)snx;
        prefix |= b << shifts[lev];
        prefmask |= bmask[lev] << shifts[lev];
        __syncthreads();
    }

    const uint32_t T = prefix;
    const int R = need;
    for (int i = tid; i < S_TOK; i += 128) {
        uint32_t k = keys[i];
        bool sel = (k > T);
        if (!sel && k == T) {
            int rank = 0;
            for (int j = 0; j < i; j++)
                if (keys[j] == T) rank++;
            sel = (rank < R);
        }
        if (sel) {
            int p = atomicAdd(&s_pos, 1);
            g_gating[e * KM + p] = __uint_as_float(k);
            g_idx[e * KM + p] = i;
            ones_out[(size_t)i * EM + e] = 1.0f;
        }
    }
}

// == GEMM body: 128-thread CTA, 128x128 tile, 4-stage cp.async, 1 sync/chunk =
// MODE 0: g_t = silu(xh @ B^T + bias)            (fp32 out)
// MODE 1: g_h[e] = gelu(gather(xh) @ B^T + bias) (fp16 out)
// MODE 2: y[idx] += gating * (g_h[e] @ B^T + b)  (fp32 atomic out)
template <int MODE>
__device__ void gemm_body(char* dynsmem, const __half* __restrict__ A,
                          const __half* __restrict__ Bw,
                          const float* __restrict__ bias, void* __restrict__ C_,
                          int M, int N, int K, int bx, int by, int e) {
    uint32_t base = (uint32_t)__cvta_generic_to_shared(dynsmem);
    base = (base + 1023u) & ~1023u;

    const int t = threadIdx.x;                 // 128 threads, 4 warps
    const int lane = t & 31, w = t >> 5;
    const int wm = w & 1, wn = w >> 1;         // warp tile 64x64
    const int g = lane >> 2, tg = lane & 3;
    const int row0 = by * 128;
    const int col0 = bx * 128;

    if (MODE == 1) {
        Bw += (size_t)e * N * K;
        bias += (size_t)e * N;
    } else if (MODE == 2) {
        A += (size_t)e * (size_t)M * K;
        Bw += (size_t)e * N * K;
        bias += (size_t)e * N;
    }

    const __half* a_src[4];
    const __half* b_src[4];
    uint32_t ab_dst[4];
#pragma unroll
    for (int j = 0; j < 4; j++) {
        int i = t + j * 128;
        int row = i >> 2, u = i & 3;
        ab_dst[j] = swzi((uint32_t)(row * 64 + u * 16));
        long arow = row0 + row;
        if (MODE == 1) arow = g_idx[e * KM + arow];
        a_src[j] = A + (size_t)arow * K + u * 8;
        b_src[j] = Bw + (size_t)(col0 + row) * K + u * 8;
    }

    float acc[4][8][4];
#pragma unroll
    for (int mt = 0; mt < 4; mt++)
#pragma unroll
        for (int nt = 0; nt < 8; nt++)
#pragma unroll
            for (int r = 0; r < 4; r++) acc[mt][nt][r] = 0.f;

    const int NC = K / KC;
    // prologue: fill stages 0..2 (groups 0..2)
#pragma unroll
    for (int st = 0; st < 3; st++) {
        uint32_t ab = base + st * STAGEB;
        uint32_t bb = ab + 8192;
        int kb = st * KC;
#pragma unroll
        for (int j = 0; j < 4; j++) cp16(ab + ab_dst[j], a_src[j] + kb);
#pragma unroll
        for (int j = 0; j < 4; j++) cp16(bb + ab_dst[j], b_src[j] + kb);
        cp_commit();
    }

    for (int c = 0; c < NC; c++) {
        cp_wait2();                 // groups <= c complete -> stage c ready
        __syncthreads();            // also protects buffer (c+3)%4 overwrite
        if (c + 3 < NC) {
            int st = (c + 3) & (NSTAGE - 1);
            uint32_t ab = base + st * STAGEB;
            uint32_t bb = ab + 8192;
            int kb = (c + 3) * KC;
#pragma unroll
            for (int j = 0; j < 4; j++) cp16(ab + ab_dst[j], a_src[j] + kb);
#pragma unroll
            for (int j = 0; j < 4; j++) cp16(bb + ab_dst[j], b_src[j] + kb);
        }
        cp_commit();

        uint32_t sa = base + (c & (NSTAGE - 1)) * STAGEB;
        uint32_t sb = sa + 8192;
#pragma unroll
        for (int ks = 0; ks < 2; ks++) {
            uint32_t af[4][4], bf[8][2];
            int aunit = (lane >> 4) + ks * 2;
#pragma unroll
            for (int mt = 0; mt < 4; mt++) {
                int r = wm * 64 + mt * 16 + (lane & 15);
                ldm_x4(af[mt], sa + swzi((uint32_t)(r * 64 + aunit * 16)));
            }
            int brow = wn * 64 + ((lane >> 4) << 3) + (lane & 7);
            int bunit = ks * 2 + ((lane >> 3) & 1);
#pragma unroll
            for (int p = 0; p < 4; p++) {
                uint32_t r4[4];
                int r = brow + p * 16;
                ldm_x4(r4, sb + swzi((uint32_t)(r * 64 + bunit * 16)));
                bf[p * 2][0] = r4[0]; bf[p * 2][1] = r4[1];
                bf[p * 2 + 1][0] = r4[2]; bf[p * 2 + 1][1] = r4[3];
            }
#pragma unroll
            for (int mt = 0; mt < 4; mt++)
#pragma unroll
                for (int nt = 0; nt < 8; nt++)
                    mma_f16(acc[mt][nt], af[mt], bf[nt]);
        }
    }

#pragma unroll
    for (int mt = 0; mt < 4; mt++) {
        int r_lo = row0 + wm * 64 + mt * 16 + g;
        int r_hi = r_lo + 8;
        int tok_lo = 0, tok_hi = 0;
        float g_lo = 0.f, g_hi = 0.f;
        if (MODE == 2) {
            tok_lo = g_idx[e * KM + r_lo];
            tok_hi = g_idx[e * KM + r_hi];
            g_lo = g_gating[e * KM + r_lo];
            g_hi = g_gating[e * KM + r_hi];
        }
#pragma unroll
        for (int nt = 0; nt < 8; nt++) {
            int col = col0 + wn * 64 + nt * 8 + 2 * tg;
            float b0 = bias[col], b1 = bias[col + 1];
            float v0 = acc[mt][nt][0] + b0, v1 = acc[mt][nt][1] + b1;
            float v2 = acc[mt][nt][2] + b0, v3 = acc[mt][nt][3] + b1;
            if (MODE == 0) {
                float* Co = (float*)C_;
                *(float2*)(Co + (size_t)r_lo * N + col) = make_float2(siluf(v0), siluf(v1));
                *(float2*)(Co + (size_t)r_hi * N + col) = make_float2(siluf(v2), siluf(v3));
            } else if (MODE == 1) {
                __half* Co = (__half*)C_ + (size_t)e * (size_t)M * N;
                __half2 lo = __floats2half2_rn(geluf(v0), geluf(v1));
                __half2 hi = __floats2half2_rn(geluf(v2), geluf(v3));
                *(__half2*)(Co + (size_t)r_lo * N + col) = lo;
                *(__half2*)(Co + (size_t)r_hi * N + col) = hi;
            } else {
                float* Co = (float*)C_;
                float* ylo = Co + (size_t)tok_lo * DM + col;
                float* yhi = Co + (size_t)tok_hi * DM + col;
                atomicAdd(ylo, g_lo * v0);
                atomicAdd(ylo + 1, g_lo * v1);
                atomicAdd(yhi, g_hi * v2);
                atomicAdd(yhi + 1, g_hi * v3);
            }
        }
    }
}

// -- launch 2: topk (8) | cap GEMM (512) | T(exp_w1) (8192) -------------------
#define G0_BLKS ((DM / 128) * (S_TOK / 128))           // 512
#define TW1_BLKS ((HM / 64) * (DM / 64) * EM)          // 8192
__global__ void __launch_bounds__(128, 2)
hgemm0_topk(const __half* __restrict__ A, const __half* __restrict__ Bw,
            const float* __restrict__ bias, float* __restrict__ Cout,
            const float* __restrict__ exp_w1, float* __restrict__ ones_out) {
    extern __shared__ char dynsmem[];
    if (blockIdx.x < 8) {
        topk128(dynsmem, blockIdx.x, ones_out);
        return;
    }
    if (blockIdx.x < 8 + G0_BLKS) {
        const int lin = blockIdx.x - 8;
        const int nx = DM / 128;
        gemm_body<0>(dynsmem, A, Bw, bias, Cout, S_TOK, DM, DM,
                     lin % nx, lin / nx, 0);
        return;
    }
    transpose64_128((float*)dynsmem, exp_w1, g_w1t, DM, HM,
                    blockIdx.x - 8 - G0_BLKS);
}

// -- launch 3: cap_out (256) | expert GEMM1 (4096) | T(exp_w2) (8192) ---------
#define G1_BLKS ((HM / 128) * (KM / 128) * EM)         // 4096
__global__ void __launch_bounds__(128, 2)
hgemm1_capout(const __half* __restrict__ A, const __half* __restrict__ Bw,
              const float* __restrict__ bias, __half* __restrict__ Cout,
              const float* __restrict__ cw2, const float* __restrict__ cb2,
              float* __restrict__ capO, const float* __restrict__ exp_w2) {
    extern __shared__ char dynsmem[];
    if (blockIdx.x < 256) {
        const int w = threadIdx.x >> 5, lane = threadIdx.x & 31;
#pragma unroll
        for (int q = 0; q < 8; q++) {
            int s = blockIdx.x * 32 + q * 4 + w;
            float acc[EM];
#pragma unroll
            for (int j = 0; j < EM; j++) acc[j] = 0.f;
            const float* tr = g_t + (size_t)s * DM;
            for (int k = lane; k < DM; k += 32) {
                float tv = tr[k];
#pragma unroll
                for (int j = 0; j < EM; j++) acc[j] += tv * cw2[k * EM + j];
            }
#pragma unroll
            for (int j = 0; j < EM; j++) {
#pragma unroll
                for (int o = 16; o > 0; o >>= 1)
                    acc[j] += __shfl_xor_sync(0xffffffffu, acc[j], o);
            }
            if (lane == 0) {
#pragma unroll
                for (int j = 0; j < EM; j++)
                    capO[(size_t)s * EM + j] = acc[j] + cb2[j];
            }
        }
        return;
    }
    if (blockIdx.x < 256 + G1_BLKS) {
        const int lin = blockIdx.x - 256;
        const int e = lin >> 9;             // 512 blocks/expert (32x16)
        const int r = lin & 511;
        gemm_body<1>(dynsmem, A, Bw, bias, Cout, KM, HM, DM, r & 31, r >> 5, e);
        return;
    }
    transpose64_128((float*)dynsmem, exp_w2, g_w2t, HM, DM,
                    blockIdx.x - 256 - G1_BLKS);
}

// -- launch 4: expert GEMM2 (scatter) -----------------------------------------
__global__ void __launch_bounds__(128, 2)
hgemm2(const __half* __restrict__ A, const __half* __restrict__ Bw,
       const float* __restrict__ bias, float* __restrict__ Y) {
    extern __shared__ char dynsmem[];
    gemm_body<2>(dynsmem, A, Bw, bias, Y, KM, DM, HM,
                 blockIdx.x, blockIdx.y, blockIdx.z);
}

// ---------------- launch -----------------------------------------------------
extern "C" void kernel_launch(void* const* d_in, const int* in_sizes, int n_in,
                              void* d_out, int out_size) {
    const float* x      = (const float*)d_in[0];
    const float* gate_w = (const float*)d_in[1];
    const float* cap_w1 = (const float*)d_in[2];
    const float* cap_b1 = (const float*)d_in[3];
    const float* cap_w2 = (const float*)d_in[4];
    const float* cap_b2 = (const float*)d_in[5];
    const float* exp_w1 = (const float*)d_in[6];
    const float* exp_b1 = (const float*)d_in[7];
    const float* exp_w2 = (const float*)d_in[8];
    const float* exp_b2 = (const float*)d_in[9];

    float* out  = (float*)d_out;
    float* y    = out;                                   // [S, D]
    float* ones = out + (size_t)S_TOK * DM;              // [S, E]
    float* cap  = ones + (size_t)S_TOK * EM;             // [S, E]

    cudaFuncSetAttribute(hgemm0_topk, cudaFuncAttributeMaxDynamicSharedMemorySize, SMEM_DYN);
    cudaFuncSetAttribute(hgemm1_capout, cudaFuncAttributeMaxDynamicSharedMemorySize, SMEM_DYN);
    cudaFuncSetAttribute(hgemm2, cudaFuncAttributeMaxDynamicSharedMemorySize, SMEM_DYN);

    __half* xh;   cudaGetSymbolAddress((void**)&xh, g_xh);
    __half* cw1t; cudaGetSymbolAddress((void**)&cw1t, g_cw1t);
    __half* w1t;  cudaGetSymbolAddress((void**)&w1t, g_w1t);
    __half* w2t;  cudaGetSymbolAddress((void**)&w2t, g_w2t);
    float*  gt;   cudaGetSymbolAddress((void**)&gt, g_t);
    __half* gh;   cudaGetSymbolAddress((void**)&gh, g_h);

    // 1: zero + x->fp16 + softmax + T(cap_w1)
    prep_kernel<<<PREP_BLKS, 256>>>(x, gate_w, cap_w1, out);

    // 2: topk | cap GEMM silu | T(exp_w1)
    hgemm0_topk<<<8 + G0_BLKS + TW1_BLKS, 128, SMEM_DYN>>>(
        xh, cw1t, cap_b1, gt, exp_w1, ones);

    // 3: cap_out | expert up-proj GEMM | T(exp_w2)
    hgemm1_capout<<<256 + G1_BLKS + (DM / 64) * (HM / 64) * EM, 128, SMEM_DYN>>>(
        xh, w1t, exp_b1, gh, cap_w2, cap_b2, cap, exp_w2);

    // 4: expert down-proj GEMM + gating scatter-add
    hgemm2<<<dim3(DM / 128, KM / 128, EM), 128, SMEM_DYN>>>(
        gh, w2t, exp_b2, y);
}

// round 10
// speedup vs baseline: 8.1840x; 1.0282x over previous
#include <cuda_runtime.h>
#include <cuda_fp16.h>
#include <cstdint>

// Problem constants
#define S_TOK 8192      // B*S_LEN tokens
#define DM    1024      // model dim
#define EM    8         // experts
#define HM    4096      // hidden
#define KM    2048      // capacity per expert

#define KC        64            // k-chunk (halves) -> 128B rows (SW128 atom)
#define STAGEB    32768         // 16KB A + 16KB B per stage (128x128 tile)
#define NSTAGE    3
#define SMEM_DYN  (NSTAGE * STAGEB + 1024)

// ---------------- scratch (device globals; no allocation allowed) -----------
__device__ float  g_scores[EM * S_TOK];            // softmaxed router scores [E,S]
__device__ float  g_gating[EM * KM];               // top-K gating values [E,K]
__device__ int    g_idx[EM * KM];                  // top-K token indices [E,K]
__device__ float  g_t[(size_t)S_TOK * DM];         // silu(x@cap_w1+b1) fp32
__device__ __half g_xh[(size_t)S_TOK * DM];        // x in fp16
__device__ __half g_h[(size_t)EM * KM * HM];       // gelu hidden [E,K,H] fp16
__device__ __half g_cw1t[(size_t)DM * DM];         // cap_w1^T fp16
__device__ __half g_w1t[(size_t)EM * HM * DM];     // w1^T per expert [H, D] fp16
__device__ __half g_w2t[(size_t)EM * DM * HM];     // w2^T per expert [D, H] fp16

// ---------------- helpers ----------------------------------------------------
__device__ __forceinline__ float siluf(float v) {
    return v / (1.0f + __expf(-v));
}
__device__ __forceinline__ float geluf(float v) {
    float c = 0.7978845608028654f * (v + 0.044715f * v * v * v);
    return 0.5f * v * (1.0f + tanhf(c));
}
__device__ __forceinline__ void ldm_x4(uint32_t* r, uint32_t addr) {
    asm volatile("ldmatrix.sync.aligned.m8n8.x4.shared.b16 {%0,%1,%2,%3}, [%4];"
                 : "=r"(r[0]), "=r"(r[1]), "=r"(r[2]), "=r"(r[3]) : "r"(addr));
}
__device__ __forceinline__ void mma_f16(float* d, const uint32_t* a, const uint32_t* b) {
    asm volatile(
        "mma.sync.aligned.m16n8k16.row.col.f32.f16.f16.f32 "
        "{%0,%1,%2,%3}, {%4,%5,%6,%7}, {%8,%9}, {%0,%1,%2,%3};"
        : "+f"(d[0]), "+f"(d[1]), "+f"(d[2]), "+f"(d[3])
        : "r"(a[0]), "r"(a[1]), "r"(a[2]), "r"(a[3]), "r"(b[0]), "r"(b[1]));
}
__device__ __forceinline__ void cp16(uint32_t dst, const void* src) {
    asm volatile("cp.async.cg.shared.global [%0], [%1], 16;" :: "r"(dst), "l"(src));
}
__device__ __forceinline__ void cp_commit() {
    asm volatile("cp.async.commit_group;");
}
__device__ __forceinline__ void cp_wait1() {
    asm volatile("cp.async.wait_group 1;");
}
__device__ __forceinline__ uint32_t swzi(uint32_t off) {      // SW128: b[6:4]^=b[9:7]
    return off ^ ((off >> 3) & 0x70);
}

// ------------- transpose64: 128-thread, tile from dynamic smem --------------
__device__ void transpose64_128(float* tile /*64*65*/, const float* in,
                                __half* out, int R, int C, int id) {
    const int tx = C / 64;
    const int per = tx * (R / 64);
    const int z = id / per, r2 = id % per;
    const int bx = (r2 % tx) * 64, by = (r2 / tx) * 64;
    in += (size_t)z * R * C;
    out += (size_t)z * R * C;
    const int t = threadIdx.x;          // 128 threads
#pragma unroll
    for (int j = 0; j < 8; j++) {
        int i = t + j * 128;
        int r = i >> 4, c4 = (i & 15) * 4;
        float4 v = *(const float4*)(in + (size_t)(by + r) * C + bx + c4);
        tile[r * 65 + c4 + 0] = v.x; tile[r * 65 + c4 + 1] = v.y;
        tile[r * 65 + c4 + 2] = v.z; tile[r * 65 + c4 + 3] = v.w;
    }
    __syncthreads();
#pragma unroll
    for (int j = 0; j < 4; j++) {
        int i = t + j * 128;
        int c = i >> 3, r8 = (i & 7) * 8;
        __half2 p0 = __floats2half2_rn(tile[(r8 + 0) * 65 + c], tile[(r8 + 1) * 65 + c]);
        __half2 p1 = __floats2half2_rn(tile[(r8 + 2) * 65 + c], tile[(r8 + 3) * 65 + c]);
        __half2 p2 = __floats2half2_rn(tile[(r8 + 4) * 65 + c], tile[(r8 + 5) * 65 + c]);
        __half2 p3 = __floats2half2_rn(tile[(r8 + 6) * 65 + c], tile[(r8 + 7) * 65 + c]);
        uint4 pk = make_uint4(*(uint32_t*)&p0, *(uint32_t*)&p1,
                              *(uint32_t*)&p2, *(uint32_t*)&p3);
        *(uint4*)(out + (size_t)(bx + c) * R + by + r8) = pk;
    }
}

// =================== PREP: zero | x2h | softmax | T(cap_w1) =================
#define ZB   512
#define XB   256
#define SMB  1024
#define T1B  ((DM / 64) * (DM / 64))              // 256
#define PREP_BLKS (ZB + XB + SMB + T1B)

__global__ void __launch_bounds__(256)
prep_kernel(const float* __restrict__ x, const float* __restrict__ gw,
            const float* __restrict__ cap_w1, float* __restrict__ outzero) {
    __shared__ float tile[64 * 65];
    const int bid = blockIdx.x;
    const int t = threadIdx.x;

    if (bid < ZB) {
        float4* p = (float4*)outzero;
        const int n4 = (S_TOK * DM + S_TOK * EM) / 4;
        for (int i = bid * 256 + t; i < n4; i += ZB * 256)
            p[i] = make_float4(0.f, 0.f, 0.f, 0.f);
        return;
    }
    if (bid < ZB + XB) {
        const int b = bid - ZB;
        const float4* xi = (const float4*)x;
        uint2* xo = (uint2*)g_xh;
        const int n8 = S_TOK * DM / 8;
        for (int i = b * 256 + t; i < n8; i += XB * 256) {
            float4 a = xi[i * 2], c = xi[i * 2 + 1];
            __half2 h0 = __floats2half2_rn(a.x, a.y);
            __half2 h1 = __floats2half2_rn(a.z, a.w);
            __half2 h2 = __floats2half2_rn(c.x, c.y);
            __half2 h3 = __floats2half2_rn(c.z, c.w);
            xo[i * 2] = make_uint2(*(uint32_t*)&h0, *(uint32_t*)&h1);
            xo[i * 2 + 1] = make_uint2(*(uint32_t*)&h2, *(uint32_t*)&h3);
        }
        return;
    }
    if (bid < ZB + XB + SMB) {
        const int b = bid - ZB - XB;
        int warp = t >> 5, lane = t & 31;
        int s = b * 8 + warp;
        float acc[EM];
#pragma unroll
        for (int e = 0; e < EM; e++) acc[e] = 0.f;
        const float* xr = x + (size_t)s * DM;
        for (int k = lane; k < DM; k += 32) {
            float xv = xr[k];
#pragma unroll
            for (int e = 0; e < EM; e++) acc[e] += xv * gw[e * DM + k];
        }
#pragma unroll
        for (int e = 0; e < EM; e++) {
#pragma unroll
            for (int o = 16; o > 0; o >>= 1)
                acc[e] += __shfl_xor_sync(0xffffffffu, acc[e], o);
        }
        if (lane == 0) {
            float mx = acc[0];
#pragma unroll
            for (int e = 1; e < EM; e++) mx = fmaxf(mx, acc[e]);
            float sum = 0.f;
#pragma unroll
            for (int e = 0; e < EM; e++) { acc[e] = __expf(acc[e] - mx); sum += acc[e]; }
            float inv = 1.0f / sum;
#pragma unroll
            for (int e = 0; e < EM; e++) g_scores[e * S_TOK + s] = acc[e] * inv;
        }
        return;
    }
    {
        const int id = bid - ZB - XB - SMB;
        const int bx = (id % (DM / 64)) * 64, by = (id / (DM / 64)) * 64;
#pragma unroll
        for (int j = 0; j < 4; j++) {
            int i = t + j * 256;
            int r = i >> 4, c4 = (i & 15) * 4;
            float4 v = *(const float4*)(cap_w1 + (size_t)(by + r) * DM + bx + c4);
            tile[r * 65 + c4 + 0] = v.x; tile[r * 65 + c4 + 1] = v.y;
            tile[r * 65 + c4 + 2] = v.z; tile[r * 65 + c4 + 3] = v.w;
        }
        __syncthreads();
#pragma unroll
        for (int j = 0; j < 2; j++) {
            int i = t + j * 256;
            int c = i >> 3, r8 = (i & 7) * 8;
            __half2 p0 = __floats2half2_rn(tile[(r8 + 0) * 65 + c], tile[(r8 + 1) * 65 + c]);
            __half2 p1 = __floats2half2_rn(tile[(r8 + 2) * 65 + c], tile[(r8 + 3) * 65 + c]);
            __half2 p2 = __floats2half2_rn(tile[(r8 + 4) * 65 + c], tile[(r8 + 5) * 65 + c]);
            __half2 p3 = __floats2half2_rn(tile[(r8 + 6) * 65 + c], tile[(r8 + 7) * 65 + c]);
            uint4 pk = make_uint4(*(uint32_t*)&p0, *(uint32_t*)&p1,
                                  *(uint32_t*)&p2, *(uint32_t*)&p3);
            *(uint4*)(g_cw1t + (size_t)(bx + c) * DM + by + r8) = pk;
        }
    }
}

// ============ topk (128-thread, 3-level radix select, exact set) ============
__device__ void topk128(char* dyn, int e, float* __restrict__ ones_out) {
    uint32_t* keys = (uint32_t*)dyn;          // 8192 words
    uint32_t* hist = keys + S_TOK;            // 2048
    uint32_t* tot = hist + 2048;              // 128
    __shared__ uint32_t sb_sel;
    __shared__ int s_pos;
    const int tid = threadIdx.x;              // 128 threads

    for (int i = tid; i < S_TOK; i += 128)
        keys[i] = __float_as_uint(g_scores[e * S_TOK + i]);
    if (tid == 0) s_pos = 0;

    uint32_t prefix = 0, prefmask = 0;
    int need = KM;
    const int shifts[3] = {21, 10, 0};
    const int binsN[3] = {2048, 2048, 1024};
    const uint32_t bmask[3] = {2047u, 2047u, 1023u};

#pragma unroll
    for (int lev = 0; lev < 3; lev++) {
        const int nb = binsN[lev];
        const int cpt = nb >> 7;
        __syncthreads();
        for (int i = tid; i < nb; i += 128) hist[i] = 0;
        __syncthreads();
        for (int i = tid; i < S_TOK; i += 128) {
            uint32_t k = keys[i];
            if ((k & prefmask) == prefix)
                atomicAdd(&hist[(k >> shifts[lev]) & bmask[lev]], 1u);
        }
        __syncthreads();
        uint32_t loc[16], mySum = 0;
        for (int j = cpt - 1; j >= 0; j--) {
            mySum += hist[tid * cpt + j];
            loc[j] = mySum;
        }
        tot[tid] = mySum;
        __syncthreads();
        for (int off = 1; off < 128; off <<= 1) {
            uint32_t v = tot[tid] + ((tid + off < 128) ? tot[tid + off] : 0u);
            __syncthreads();
            tot[tid] = v;
            __syncthreads();
        }
        uint32_t above = tot[tid] - mySum;
        for (int j = 0; j < cpt; j++) hist[tid * cpt + j] = loc[j] + above;
        __syncthreads();
        for (int i = tid; i < nb; i += 128) {
            uint32_t s = hist[i];
            uint32_t snx = (i + 1 < nb) ? hist[i + 1] : 0u;
            if (s >= (uint32_t)need && snx < (uint32_t)need) sb_sel = (uint32_t)i;
        }
        __syncthreads();
        uint32_t b = sb_sel;
        uint32_t snx = (b + 1 < (uint32_t)nb) ? hist[b + 1] : 0u;
        need -= (int)snx;
        prefix |= b << shifts[lev];
        prefmask |= bmask[lev] << shifts[lev];
        __syncthreads();
    }

    const uint32_t T = prefix;
    const int R = need;
    for (int i = tid; i < S_TOK; i += 128) {
        uint32_t k = keys[i];
        bool sel = (k > T);
        if (!sel && k == T) {
            int rank = 0;
            for (int j = 0; j < i; j++)
                if (keys[j] == T) rank++;
            sel = (rank < R);
        }
        if (sel) {
            int p = atomicAdd(&s_pos, 1);
            g_gating[e * KM + p] = __uint_as_float(k);
            g_idx[e * KM + p] = i;
            ones_out[(size_t)i * EM + e] = 1.0f;
        }
    }
}

// == GEMM body: 128-thr CTA, 128x128 tile, KC=64 (128B rows), 3-stage async ==
// MODE 0: g_t = silu(xh @ B^T + bias)            (fp32 out)
// MODE 1: g_h[e] = gelu(gather(xh) @ B^T + bias) (fp16 out)
// MODE 2: y[idx] += gating * (g_h[e] @ B^T + b)  (fp32 atomic out)
template <int MODE>
__device__ void gemm_body(char* dynsmem, const __half* __restrict__ A,
                          const __half* __restrict__ Bw,
                          const float* __restrict__ bias, void* __restrict__ C_,
                          int M, int N, int K, int bx, int by, int e) {
    uint32_t base = (uint32_t)__cvta_generic_to_shared(dynsmem);
    base = (base + 1023u) & ~1023u;

    const int t = threadIdx.x;                 // 128 threads, 4 warps
    const int lane = t & 31, w = t >> 5;
    const int wm = w & 1, wn = w >> 1;         // warp tile 64x64
    const int g = lane >> 2, tg = lane & 3;
    const int row0 = by * 128;
    const int col0 = bx * 128;

    if (MODE == 1) {
        Bw += (size_t)e * N * K;
        bias += (size_t)e * N;
    } else if (MODE == 2) {
        A += (size_t)e * (size_t)M * K;
        Bw += (size_t)e * N * K;
        bias += (size_t)e * N;
    }

    // loader: each thread owns unit column u (16B) of rows r0+16j, j=0..7
    const int r0 = t >> 3, u = t & 7;
    uint32_t dstoff[8];
#pragma unroll
    for (int j = 0; j < 8; j++)
        dstoff[j] = swzi((uint32_t)((r0 + 16 * j) * 128 + u * 16));

    const __half* aPj[8];
#pragma unroll
    for (int j = 0; j < 8; j++) {
        long arow = row0 + r0 + 16 * j;
        if (MODE == 1) arow = g_idx[e * KM + arow];
        aPj[j] = A + (size_t)arow * K + u * 8;
    }
    const __half* bP0 = Bw + (size_t)(col0 + r0) * K + u * 8;
    const size_t bstep = (size_t)16 * K;

    float acc[4][8][4];
#pragma unroll
    for (int mt = 0; mt < 4; mt++)
#pragma unroll
        for (int nt = 0; nt < 8; nt++)
#pragma unroll
            for (int r = 0; r < 4; r++) acc[mt][nt][r] = 0.f;

    const int NC = K / KC;
    // prologue: stages 0,1
#pragma unroll
    for (int st = 0; st < 2; st++) {
        uint32_t ab = base + st * STAGEB;
        uint32_t bb = ab + 16384;
        int kb = st * KC;
#pragma unroll
        for (int j = 0; j < 8; j++) cp16(ab + dstoff[j], aPj[j] + kb);
#pragma unroll
        for (int j = 0; j < 8; j++) cp16(bb + dstoff[j], bP0 + bstep * j + kb);
        cp_commit();
    }

    for (int c = 0; c < NC; c++) {
        cp_wait1();                 // group c complete
        __syncthreads();            // buffer (c+2)%3 free (read in iter c-1)
        if (c + 2 < NC) {
            int st = (c + 2) % NSTAGE;
            uint32_t ab = base + st * STAGEB;
            uint32_t bb = ab + 16384;
            int kb = (c + 2) * KC;
#pragma unroll
            for (int j = 0; j < 8; j++) cp16(ab + dstoff[j], aPj[j] + kb);
#pragma unroll
            for (int j = 0; j < 8; j++) cp16(bb + dstoff[j], bP0 + bstep * j + kb);
        }
        cp_commit();

        uint32_t sa = base + (c % NSTAGE) * STAGEB;
        uint32_t sb = sa + 16384;
#pragma unroll
        for (int ks = 0; ks < 4; ks++) {
            uint32_t af[4][4], bf[8][2];
            int aunit = (lane >> 4) + ks * 2;
#pragma unroll
            for (int mt = 0; mt < 4; mt++) {
                int r = wm * 64 + mt * 16 + (lane & 15);
                ldm_x4(af[mt], sa + swzi((uint32_t)(r * 128 + aunit * 16)));
            }
            int brow = wn * 64 + ((lane >> 4) << 3) + (lane & 7);
            int bunit = ks * 2 + ((lane >> 3) & 1);
#pragma unroll
            for (int p = 0; p < 4; p++) {
                uint32_t r4[4];
                int r = brow + p * 16;
                ldm_x4(r4, sb + swzi((uint32_t)(r * 128 + bunit * 16)));
                bf[p * 2][0] = r4[0]; bf[p * 2][1] = r4[1];
                bf[p * 2 + 1][0] = r4[2]; bf[p * 2 + 1][1] = r4[3];
            }
#pragma unroll
            for (int mt = 0; mt < 4; mt++)
#pragma unroll
                for (int nt = 0; nt < 8; nt++)
                    mma_f16(acc[mt][nt], af[mt], bf[nt]);
        }
    }

#pragma unroll
    for (int mt = 0; mt < 4; mt++) {
        int r_lo = row0 + wm * 64 + mt * 16 + g;
        int r_hi = r_lo + 8;
        int tok_lo = 0, tok_hi = 0;
        float g_lo = 0.f, g_hi = 0.f;
        if (MODE == 2) {
            tok_lo = g_idx[e * KM + r_lo];
            tok_hi = g_idx[e * KM + r_hi];
            g_lo = g_gating[e * KM + r_lo];
            g_hi = g_gating[e * KM + r_hi];
        }
#pragma unroll
        for (int nt = 0; nt < 8; nt++) {
            int col = col0 + wn * 64 + nt * 8 + 2 * tg;
            float b0 = bias[col], b1 = bias[col + 1];
            float v0 = acc[mt][nt][0] + b0, v1 = acc[mt][nt][1] + b1;
            float v2 = acc[mt][nt][2] + b0, v3 = acc[mt][nt][3] + b1;
            if (MODE == 0) {
                float* Co = (float*)C_;
                *(float2*)(Co + (size_t)r_lo * N + col) = make_float2(siluf(v0), siluf(v1));
                *(float2*)(Co + (size_t)r_hi * N + col) = make_float2(siluf(v2), siluf(v3));
            } else if (MODE == 1) {
                __half* Co = (__half*)C_ + (size_t)e * (size_t)M * N;
                __half2 lo = __floats2half2_rn(geluf(v0), geluf(v1));
                __half2 hi = __floats2half2_rn(geluf(v2), geluf(v3));
                *(__half2*)(Co + (size_t)r_lo * N + col) = lo;
                *(__half2*)(Co + (size_t)r_hi * N + col) = hi;
            } else {
                float* Co = (float*)C_;
                float* ylo = Co + (size_t)tok_lo * DM + col;
                float* yhi = Co + (size_t)tok_hi * DM + col;
                atomicAdd(ylo, g_lo * v0);
                atomicAdd(ylo + 1, g_lo * v1);
                atomicAdd(yhi, g_hi * v2);
                atomicAdd(yhi + 1, g_hi * v3);
            }
        }
    }
}

// -- launch 2: topk (8) | cap GEMM (512) | T(exp_w1) (8192) -------------------
#define G0_BLKS ((DM / 128) * (S_TOK / 128))           // 512
#define TW1_BLKS ((HM / 64) * (DM / 64) * EM)          // 8192
__global__ void __launch_bounds__(128, 2)
hgemm0_topk(const __half* __restrict__ A, const __half* __restrict__ Bw,
            const float* __restrict__ bias, float* __restrict__ Cout,
            const float* __restrict__ exp_w1, float* __restrict__ ones_out) {
    extern __shared__ char dynsmem[];
    if (blockIdx.x < 8) {
        topk128(dynsmem, blockIdx.x, ones_out);
        return;
    }
    if (blockIdx.x < 8 + G0_BLKS) {
        const int lin = blockIdx.x - 8;
        const int nx = DM / 128;
        gemm_body<0>(dynsmem, A, Bw, bias, Cout, S_TOK, DM, DM,
                     lin % nx, lin / nx, 0);
        return;
    }
    transpose64_128((float*)dynsmem, exp_w1, g_w1t, DM, HM,
                    blockIdx.x - 8 - G0_BLKS);
}

// -- launch 3: cap_out (256) | expert GEMM1 (4096) | T(exp_w2) (8192) ---------
#define G1_BLKS ((HM / 128) * (KM / 128) * EM)         // 4096
__global__ void __launch_bounds__(128, 2)
hgemm1_capout(const __half* __restrict__ A, const __half* __restrict__ Bw,
              const float* __restrict__ bias, __half* __restrict__ Cout,
              const float* __restrict__ cw2, const float* __restrict__ cb2,
              float* __restrict__ capO, const float* __restrict__ exp_w2) {
    extern __shared__ char dynsmem[];
    if (blockIdx.x < 256) {
        const int w = threadIdx.x >> 5, lane = threadIdx.x & 31;
#pragma unroll
        for (int q = 0; q < 8; q++) {
            int s = blockIdx.x * 32 + q * 4 + w;
            float acc[EM];
#pragma unroll
            for (int j = 0; j < EM; j++) acc[j] = 0.f;
            const float* tr = g_t + (size_t)s * DM;
            for (int k = lane; k < DM; k += 32) {
                float tv = tr[k];
#pragma unroll
                for (int j = 0; j < EM; j++) acc[j] += tv * cw2[k * EM + j];
            }
#pragma unroll
            for (int j = 0; j < EM; j++) {
#pragma unroll
                for (int o = 16; o > 0; o >>= 1)
                    acc[j] += __shfl_xor_sync(0xffffffffu, acc[j], o);
            }
            if (lane == 0) {
#pragma unroll
                for (int j = 0; j < EM; j++)
                    capO[(size_t)s * EM + j] = acc[j] + cb2[j];
            }
        }
        return;
    }
    if (blockIdx.x < 256 + G1_BLKS) {
        const int lin = blockIdx.x - 256;
        const int e = lin >> 9;             // 512 blocks/expert (32x16)
        const int r = lin & 511;
        gemm_body<1>(dynsmem, A, Bw, bias, Cout, KM, HM, DM, r & 31, r >> 5, e);
        return;
    }
    transpose64_128((float*)dynsmem, exp_w2, g_w2t, HM, DM,
                    blockIdx.x - 256 - G1_BLKS);
}

// -- launch 4: expert GEMM2 (scatter) -----------------------------------------
__global__ void __launch_bounds__(128, 2)
hgemm2(const __half* __restrict__ A, const __half* __restrict__ Bw,
       const float* __restrict__ bias, float* __restrict__ Y) {
    extern __shared__ char dynsmem[];
    gemm_body<2>(dynsmem, A, Bw, bias, Y, KM, DM, HM,
                 blockIdx.x, blockIdx.y, blockIdx.z);
}

// ---------------- launch -----------------------------------------------------
extern "C" void kernel_launch(void* const* d_in, const int* in_sizes, int n_in,
                              void* d_out, int out_size) {
    const float* x      = (const float*)d_in[0];
    const float* gate_w = (const float*)d_in[1];
    const float* cap_w1 = (const float*)d_in[2];
    const float* cap_b1 = (const float*)d_in[3];
    const float* cap_w2 = (const float*)d_in[4];
    const float* cap_b2 = (const float*)d_in[5];
    const float* exp_w1 = (const float*)d_in[6];
    const float* exp_b1 = (const float*)d_in[7];
    const float* exp_w2 = (const float*)d_in[8];
    const float* exp_b2 = (const float*)d_in[9];

    float* out  = (float*)d_out;
    float* y    = out;                                   // [S, D]
    float* ones = out + (size_t)S_TOK * DM;              // [S, E]
    float* cap  = ones + (size_t)S_TOK * EM;             // [S, E]

    cudaFuncSetAttribute(hgemm0_topk, cudaFuncAttributeMaxDynamicSharedMemorySize, SMEM_DYN);
    cudaFuncSetAttribute(hgemm1_capout, cudaFuncAttributeMaxDynamicSharedMemorySize, SMEM_DYN);
    cudaFuncSetAttribute(hgemm2, cudaFuncAttributeMaxDynamicSharedMemorySize, SMEM_DYN);

    __half* xh;   cudaGetSymbolAddress((void**)&xh, g_xh);
    __half* cw1t; cudaGetSymbolAddress((void**)&cw1t, g_cw1t);
    __half* w1t;  cudaGetSymbolAddress((void**)&w1t, g_w1t);
    __half* w2t;  cudaGetSymbolAddress((void**)&w2t, g_w2t);
    float*  gt;   cudaGetSymbolAddress((void**)&gt, g_t);
    __half* gh;   cudaGetSymbolAddress((void**)&gh, g_h);

    // 1: zero + x->fp16 + softmax + T(cap_w1)
    prep_kernel<<<PREP_BLKS, 256>>>(x, gate_w, cap_w1, out);

    // 2: topk | cap GEMM silu | T(exp_w1)
    hgemm0_topk<<<8 + G0_BLKS + TW1_BLKS, 128, SMEM_DYN>>>(
        xh, cw1t, cap_b1, gt, exp_w1, ones);

    // 3: cap_out | expert up-proj GEMM | T(exp_w2)
    hgemm1_capout<<<256 + G1_BLKS + (DM / 64) * (HM / 64) * EM, 128, SMEM_DYN>>>(
        xh, w1t, exp_b1, gh, cap_w2, cap_b2, cap, exp_w2);

    // 4: expert down-proj GEMM + gating scatter-add
    hgemm2<<<dim3(DM / 128, KM / 128, EM), 128, SMEM_DYN>>>(
        gh, w2t, exp_b2, y);
}